// round 1
// baseline (speedup 1.0000x reference)
#include <cuda_runtime.h>

// Shapes
#define Bz 2
#define Tt 768
#define tt 256
#define Cc 768
#define Hh 12
#define Dd 64
#define FC 3072
#define Vv 512

// Scratch (allocation-free: __device__ globals)
__device__ float g_x[Bz * Tt * Cc];
__device__ float g_h[Bz * Tt * Cc];
__device__ float g_y[Bz * Tt * Cc];
__device__ float g_big[Bz * Tt * FC];   // qkv (1536x2304) or mlp hidden (1536x3072)

// ---------------------------------------------------------------------------
// Generic tiled GEMM: Out[m, n] (+)= act( sum_k In[m,k] * W[n,k] + bias[n] )
// Block tile 128(M) x 64(N), 256 threads, 8x4 micro-tile, K-tile 16.
// MODE 0: write; MODE 1: GELU(exact) then write; MODE 2: residual add.
// Grid: (N/64, M/128). M must be multiple of 128, N multiple of 64.
// ---------------------------------------------------------------------------
template <int MODE>
__global__ __launch_bounds__(256) void gemm_kernel(
    const float* __restrict__ In, int ldIn,
    const float* __restrict__ W,            // [N][K] row-major
    const float* __restrict__ bias,         // [N] or nullptr
    float* __restrict__ Out, int ldOut,
    int K) {
  __shared__ float As[16][132];  // [k][m] transposed, padded
  __shared__ float Bs[16][68];   // [k][n] transposed, padded

  const int tid = threadIdx.x;
  const int tx = tid & 15;        // n micro (4 cols)
  const int ty = tid >> 4;        // m micro (8 rows)
  const int m0 = blockIdx.y * 128;
  const int n0 = blockIdx.x * 64;

  const int lr = tid >> 2;          // 0..63 load row
  const int lc = (tid & 3) * 4;     // k sub-offset {0,4,8,12}

  float acc[8][4];
#pragma unroll
  for (int r = 0; r < 8; r++)
#pragma unroll
    for (int c = 0; c < 4; c++) acc[r][c] = 0.f;

  const bool aligned = ((ldIn & 3) == 0) && ((K & 3) == 0);

  for (int kt = 0; kt < K; kt += 16) {
    if (aligned && (kt + 16 <= K)) {
      float4 a0 = *(const float4*)(In + (size_t)(m0 + lr) * ldIn + kt + lc);
      float4 a1 = *(const float4*)(In + (size_t)(m0 + lr + 64) * ldIn + kt + lc);
      float4 b0 = *(const float4*)(W + (size_t)(n0 + lr) * K + kt + lc);
      As[lc + 0][lr] = a0.x; As[lc + 1][lr] = a0.y; As[lc + 2][lr] = a0.z; As[lc + 3][lr] = a0.w;
      As[lc + 0][lr + 64] = a1.x; As[lc + 1][lr + 64] = a1.y; As[lc + 2][lr + 64] = a1.z; As[lc + 3][lr + 64] = a1.w;
      Bs[lc + 0][lr] = b0.x; Bs[lc + 1][lr] = b0.y; Bs[lc + 2][lr] = b0.z; Bs[lc + 3][lr] = b0.w;
    } else {
#pragma unroll
      for (int q = 0; q < 4; q++) {
        int k = kt + lc + q;
        float av0 = 0.f, av1 = 0.f, bv = 0.f;
        if (k < K) {
          av0 = In[(size_t)(m0 + lr) * ldIn + k];
          av1 = In[(size_t)(m0 + lr + 64) * ldIn + k];
          bv = W[(size_t)(n0 + lr) * K + k];
        }
        As[lc + q][lr] = av0;
        As[lc + q][lr + 64] = av1;
        Bs[lc + q][lr] = bv;
      }
    }
    __syncthreads();
#pragma unroll
    for (int kk = 0; kk < 16; kk++) {
      float4 t0 = *(const float4*)&As[kk][ty * 8];
      float4 t1 = *(const float4*)&As[kk][ty * 8 + 4];
      float4 t2 = *(const float4*)&Bs[kk][tx * 4];
      float a[8] = {t0.x, t0.y, t0.z, t0.w, t1.x, t1.y, t1.z, t1.w};
      float bb[4] = {t2.x, t2.y, t2.z, t2.w};
#pragma unroll
      for (int r = 0; r < 8; r++)
#pragma unroll
        for (int c = 0; c < 4; c++) acc[r][c] += a[r] * bb[c];
    }
    __syncthreads();
  }

  float bv[4];
#pragma unroll
  for (int c = 0; c < 4; c++) bv[c] = bias ? bias[n0 + tx * 4 + c] : 0.f;

#pragma unroll
  for (int r = 0; r < 8; r++) {
    float* op = Out + (size_t)(m0 + ty * 8 + r) * ldOut + n0 + tx * 4;
    float v[4];
#pragma unroll
    for (int c = 0; c < 4; c++) v[c] = acc[r][c] + bv[c];
    if (MODE == 1) {
#pragma unroll
      for (int c = 0; c < 4; c++)
        v[c] = 0.5f * v[c] * (1.f + erff(v[c] * 0.7071067811865476f));
    }
    if (MODE == 2) {
      float4 prev = *(const float4*)op;
      v[0] += prev.x; v[1] += prev.y; v[2] += prev.z; v[3] += prev.w;
    }
    float4 o = {v[0], v[1], v[2], v[3]};
    *(float4*)op = o;
  }
}

// ---------------------------------------------------------------------------
// LayerNorm: one block per row (C=768), 256 threads x 3 elems.
// ---------------------------------------------------------------------------
__global__ __launch_bounds__(256) void ln_kernel(
    const float* __restrict__ x, const float* __restrict__ w,
    const float* __restrict__ b, float* __restrict__ out) {
  const int row = blockIdx.x;
  const int tid = threadIdx.x;
  const float* xr = x + (size_t)row * Cc;
  float v0 = xr[tid], v1 = xr[tid + 256], v2 = xr[tid + 512];
  __shared__ float red[8];

  float s = v0 + v1 + v2;
#pragma unroll
  for (int o = 16; o > 0; o >>= 1) s += __shfl_xor_sync(0xffffffffu, s, o);
  if ((tid & 31) == 0) red[tid >> 5] = s;
  __syncthreads();
  float tot = red[0] + red[1] + red[2] + red[3] + red[4] + red[5] + red[6] + red[7];
  float mean = tot * (1.f / 768.f);

  float d0 = v0 - mean, d1 = v1 - mean, d2 = v2 - mean;
  float sq = d0 * d0 + d1 * d1 + d2 * d2;
  __syncthreads();
#pragma unroll
  for (int o = 16; o > 0; o >>= 1) sq += __shfl_xor_sync(0xffffffffu, sq, o);
  if ((tid & 31) == 0) red[tid >> 5] = sq;
  __syncthreads();
  float var = (red[0] + red[1] + red[2] + red[3] + red[4] + red[5] + red[6] + red[7]) * (1.f / 768.f);
  float inv = rsqrtf(var + 1e-5f);

  float* orow = out + (size_t)row * Cc;
  orow[tid] = d0 * inv * w[tid] + b[tid];
  orow[tid + 256] = d1 * inv * w[tid + 256] + b[tid + 256];
  orow[tid + 512] = d2 * inv * w[tid + 512] + b[tid + 512];
}

// ---------------------------------------------------------------------------
// Embed: x[:, :t] += pos ; x[:, t:2t] = tok_up[idx] + pos ; x[:, 2t:] = tok_down[idx] + pos
// ---------------------------------------------------------------------------
__global__ __launch_bounds__(256) void embed_kernel(
    const int* __restrict__ iu, const int* __restrict__ idn,
    const float* __restrict__ tu, const float* __restrict__ td,
    const float* __restrict__ pos, float* __restrict__ x) {
  int g = blockIdx.x * 256 + threadIdx.x;  // < Bz*Tt*Cc
  int c = g % Cc;
  int row = g / Cc;
  int i = row % Tt;
  int b = row / Tt;
  float p = pos[i * Cc + c];
  if (i < tt) {
    x[g] += p;
  } else if (i < 2 * tt) {
    x[g] = tu[(size_t)iu[b * tt + (i - tt)] * Cc + c] + p;
  } else {
    x[g] = td[(size_t)idn[b * tt + (i - 2 * tt)] * Cc + c] + p;
  }
}

// ---------------------------------------------------------------------------
// Attention: flash-style, one block per (b, h, 64-query tile).
// qkv buffer layout: [B*T, 3*C] rows from QKV GEMM (q at +0, k at +768, v at +1536,
// per-head offset h*64). Mask: (j % 256) <= (i % 256); tiles of 64 align so a
// KV tile is fully-allowed (kt%4 < qt%4), diagonal (==), or skipped (>).
// ---------------------------------------------------------------------------
__global__ __launch_bounds__(256) void attn_kernel(
    const float* __restrict__ qkv, float* __restrict__ y) {
  const int qt = blockIdx.x;  // 0..11
  const int h = blockIdx.y;   // 0..11
  const int b = blockIdx.z;   // 0..1
  const int tid = threadIdx.x;
  const int tx = tid & 15;    // key/dim micro (4)
  const int ty = tid >> 4;    // query micro (4)

  __shared__ float Qt[64][68];  // [d][i]
  __shared__ float Kt[64][68];  // [d][j]
  __shared__ float Vs[64][68];  // [j][d]
  __shared__ float Ps[64][68];  // [j][i]

  // Load Q tile transposed
  {
    int i = tid >> 2;
    int c4 = tid & 3;
    const float* qrow = qkv + (size_t)(b * Tt + qt * 64 + i) * (3 * Cc) + h * 64;
#pragma unroll
    for (int s2 = 0; s2 < 4; s2++) {
      int d0 = (c4 + 4 * s2) * 4;
      float4 v = *(const float4*)(qrow + d0);
      Qt[d0 + 0][i] = v.x; Qt[d0 + 1][i] = v.y; Qt[d0 + 2][i] = v.z; Qt[d0 + 3][i] = v.w;
    }
  }

  float m[4], l[4], acc[4][4];
#pragma unroll
  for (int r = 0; r < 4; r++) {
    m[r] = -1e30f; l[r] = 0.f;
#pragma unroll
    for (int c = 0; c < 4; c++) acc[r][c] = 0.f;
  }
  const int a = qt & 3;

  for (int kt = 0; kt < 12; kt++) {
    if ((kt & 3) > a) continue;
    const bool diag = ((kt & 3) == a);
    __syncthreads();  // prior PV done (and Q visible on first pass after next sync)
    {
      int j = tid >> 2;
      int c4 = tid & 3;
      const float* krow = qkv + (size_t)(b * Tt + kt * 64 + j) * (3 * Cc) + h * 64 + Cc;
      const float* vrow = krow + Cc;
#pragma unroll
      for (int s2 = 0; s2 < 4; s2++) {
        int d0 = (c4 + 4 * s2) * 4;
        float4 kv = *(const float4*)(krow + d0);
        Kt[d0 + 0][j] = kv.x; Kt[d0 + 1][j] = kv.y; Kt[d0 + 2][j] = kv.z; Kt[d0 + 3][j] = kv.w;
        float4 vv = *(const float4*)(vrow + d0);
        *(float4*)&Vs[j][d0] = vv;
      }
    }
    __syncthreads();

    // S = Q K^T (4x4 per thread): rows i = ty*4+r, cols j = tx*4+c
    float sv[4][4];
#pragma unroll
    for (int r = 0; r < 4; r++)
#pragma unroll
      for (int c = 0; c < 4; c++) sv[r][c] = 0.f;
#pragma unroll
    for (int d = 0; d < 64; d++) {
      float4 q4 = *(const float4*)&Qt[d][ty * 4];
      float4 k4 = *(const float4*)&Kt[d][tx * 4];
      float qa[4] = {q4.x, q4.y, q4.z, q4.w};
      float kb[4] = {k4.x, k4.y, k4.z, k4.w};
#pragma unroll
      for (int r = 0; r < 4; r++)
#pragma unroll
        for (int c = 0; c < 4; c++) sv[r][c] += qa[r] * kb[c];
    }

    // scale + mask + online softmax (row groups of 16 lanes)
#pragma unroll
    for (int r = 0; r < 4; r++) {
      float rowmax = -1e30f;
#pragma unroll
      for (int c = 0; c < 4; c++) {
        float s = sv[r][c] * 0.125f;
        if (diag && (tx * 4 + c > ty * 4 + r)) s = -1e30f;
        sv[r][c] = s;
        rowmax = fmaxf(rowmax, s);
      }
#pragma unroll
      for (int o = 1; o < 16; o <<= 1)
        rowmax = fmaxf(rowmax, __shfl_xor_sync(0xffffffffu, rowmax, o));
      float mn = fmaxf(m[r], rowmax);
      float corr = __expf(m[r] - mn);
      float rs = 0.f;
#pragma unroll
      for (int c = 0; c < 4; c++) {
        float p = __expf(sv[r][c] - mn);
        sv[r][c] = p;
        rs += p;
      }
#pragma unroll
      for (int o = 1; o < 16; o <<= 1) rs += __shfl_xor_sync(0xffffffffu, rs, o);
      l[r] = l[r] * corr + rs;
      m[r] = mn;
#pragma unroll
      for (int c = 0; c < 4; c++) acc[r][c] *= corr;
    }

    // store P transposed [j][i]
#pragma unroll
    for (int r = 0; r < 4; r++)
#pragma unroll
      for (int c = 0; c < 4; c++) Ps[tx * 4 + c][ty * 4 + r] = sv[r][c];
    __syncthreads();

    // PV: acc[r][c] += sum_j P[j][i] * V[j][d]
#pragma unroll
    for (int j = 0; j < 64; j++) {
      float4 p4 = *(const float4*)&Ps[j][ty * 4];
      float4 v4 = *(const float4*)&Vs[j][tx * 4];
      float pp[4] = {p4.x, p4.y, p4.z, p4.w};
      float vv[4] = {v4.x, v4.y, v4.z, v4.w};
#pragma unroll
      for (int r = 0; r < 4; r++)
#pragma unroll
        for (int c = 0; c < 4; c++) acc[r][c] += pp[r] * vv[c];
    }
  }

  // write y[b, qi, h*64 + d] = acc / l
#pragma unroll
  for (int r = 0; r < 4; r++) {
    float inv = 1.f / l[r];
    float4 o = {acc[r][0] * inv, acc[r][1] * inv, acc[r][2] * inv, acc[r][3] * inv};
    *(float4*)(y + (size_t)(b * Tt + qt * 64 + ty * 4 + r) * Cc + h * 64 + tx * 4) = o;
  }
}

// ---------------------------------------------------------------------------
// Launcher
// ---------------------------------------------------------------------------
extern "C" void kernel_launch(void* const* d_in, const int* in_sizes, int n_in,
                              void* d_out, int out_size) {
  const int* idx_up = nullptr; const int* idx_down = nullptr;
  const float *cond = 0, *tok_up = 0, *tok_down = 0, *pos = 0, *cond_w = 0, *cond_b = 0;
  const float *lnf_w = 0, *lnf_b = 0, *hup = 0, *hdn = 0;
  const float *ln1[2] = {0, 0}, *ln2[2] = {0, 0}, *qkvw[2] = {0, 0}, *qkvb[2] = {0, 0};
  const float *projw[2] = {0, 0}, *projb[2] = {0, 0};
  const float *fc1w[2] = {0, 0}, *fc1b[2] = {0, 0}, *fc2w[2] = {0, 0}, *fc2b[2] = {0, 0};

  int c512 = 0, c393 = 0, c768 = 0, c9216 = 0, cqw = 0, cqb = 0, cpw = 0, c4608 = 0,
      cfw = 0, cfb = 0;
  for (int i = 0; i < n_in; i++) {
    const float* f = (const float*)d_in[i];
    switch (in_sizes[i]) {
      case 512:       if (c512 == 0) idx_up = (const int*)f; else idx_down = (const int*)f; c512++; break;
      case 224256:    cond = f; break;
      case 393216:    if (c393 == 0) tok_up = f; else if (c393 == 1) tok_down = f;
                      else if (c393 == 2) hup = f; else hdn = f; c393++; break;
      case 589824:    pos = f; break;
      case 336384:    cond_w = f; break;
      case 768:       if (c768 == 0) cond_b = f; else if (c768 == 1) lnf_w = f; else lnf_b = f; c768++; break;
      case 9216:      if (c9216 == 0) ln1[0] = f; else if (c9216 == 1) ln2[0] = f;
                      else if (c9216 == 2) ln1[1] = f; else ln2[1] = f; c9216++; break;
      case 10616832:  qkvw[cqw++] = f; break;
      case 13824:     qkvb[cqb++] = f; break;
      case 3538944:   projw[cpw++] = f; break;
      case 4608:      if (c4608 == 0) projb[0] = f; else if (c4608 == 1) fc2b[0] = f;
                      else if (c4608 == 2) projb[1] = f; else fc2b[1] = f; c4608++; break;
      case 14155776:  if (cfw == 0) fc1w[0] = f; else if (cfw == 1) fc2w[0] = f;
                      else if (cfw == 2) fc1w[1] = f; else fc2w[1] = f; cfw++; break;
      case 18432:     fc1b[cfb++] = f; break;
      default: break;
    }
  }

  float *x, *h, *y, *big;
  cudaGetSymbolAddress((void**)&x, g_x);
  cudaGetSymbolAddress((void**)&h, g_h);
  cudaGetSymbolAddress((void**)&y, g_y);
  cudaGetSymbolAddress((void**)&big, g_big);

  // --- Embed: cond GEMM per batch, then pos + token rows ---
  for (int b = 0; b < Bz; b++)
    gemm_kernel<0><<<dim3(Cc / 64, tt / 128), 256>>>(
        cond + (size_t)b * tt * 438, 438, cond_w, cond_b, x + (size_t)b * Tt * Cc, Cc, 438);
  embed_kernel<<<(Bz * Tt * Cc) / 256, 256>>>(idx_up, idx_down, tok_up, tok_down, pos, x);

  // --- 2 stacks x 6 blocks ---
  for (int st = 0; st < 2; st++) {
    for (int l = 0; l < 6; l++) {
      const float* w1 = ln1[st] + (size_t)l * 2 * Cc;
      ln_kernel<<<Bz * Tt, 256>>>(x, w1, w1 + Cc, h);
      gemm_kernel<0><<<dim3(3 * Cc / 64, Bz * Tt / 128), 256>>>(
          h, Cc, qkvw[st] + (size_t)l * 3 * Cc * Cc, qkvb[st] + (size_t)l * 3 * Cc,
          big, 3 * Cc, Cc);
      attn_kernel<<<dim3(Tt / 64, Hh, Bz), 256>>>(big, y);
      gemm_kernel<2><<<dim3(Cc / 64, Bz * Tt / 128), 256>>>(
          y, Cc, projw[st] + (size_t)l * Cc * Cc, projb[st] + (size_t)l * Cc, x, Cc, Cc);
      const float* w2 = ln2[st] + (size_t)l * 2 * Cc;
      ln_kernel<<<Bz * Tt, 256>>>(x, w2, w2 + Cc, h);
      gemm_kernel<1><<<dim3(FC / 64, Bz * Tt / 128), 256>>>(
          h, Cc, fc1w[st] + (size_t)l * FC * Cc, fc1b[st] + (size_t)l * FC, big, FC, Cc);
      gemm_kernel<2><<<dim3(Cc / 64, Bz * Tt / 128), 256>>>(
          big, FC, fc2w[st] + (size_t)l * Cc * FC, fc2b[st] + (size_t)l * Cc, x, Cc, FC);
    }
  }

  // --- Final LN + heads ---
  ln_kernel<<<Bz * Tt, 256>>>(x, lnf_w, lnf_b, h);
  float* out = (float*)d_out;
  for (int b = 0; b < Bz; b++) {
    gemm_kernel<0><<<dim3(Vv / 64, tt / 128), 256>>>(
        h + (size_t)(b * Tt + tt) * Cc, Cc, hup, nullptr, out + (size_t)b * tt * Vv, Vv, Cc);
    gemm_kernel<0><<<dim3(Vv / 64, tt / 128), 256>>>(
        h + (size_t)(b * Tt + 2 * tt) * Cc, Cc, hdn, nullptr,
        out + (size_t)Bz * tt * Vv / 1 / 2 * 0 + (size_t)tt * Vv * Bz + (size_t)b * tt * Vv - (size_t)tt * Vv * Bz + (size_t)(Bz * tt * Vv) + 0, Vv, Cc);
  }
  // NOTE: the expression above must place logits_down at out + B*t*V; rewrite clearly:
  // (kept simple below — the above line is overridden by relaunching correctly)
  for (int b = 0; b < Bz; b++) {
    gemm_kernel<0><<<dim3(Vv / 64, tt / 128), 256>>>(
        h + (size_t)(b * Tt + 2 * tt) * Cc, Cc, hdn, nullptr,
        out + (size_t)(Bz * tt * Vv) + (size_t)b * tt * Vv, Vv, Cc);
  }
  (void)out_size; (void)n_in;
}

// round 2
// speedup vs baseline: 1.3850x; 1.3850x over previous
#include <cuda_runtime.h>
#include <math.h>

// Shapes
#define Bz 2
#define Tt 768
#define tt 256
#define Cc 768
#define Hh 12
#define FC 3072
#define Vv 512

// Scratch (allocation-free: __device__ globals)
__device__ float g_x[Bz * Tt * Cc];
__device__ float g_h[Bz * Tt * Cc];
__device__ float g_y[Bz * Tt * Cc];
__device__ float g_big[Bz * Tt * FC];

// ---------------------------------------------------------------------------
// tf32 helpers
// ---------------------------------------------------------------------------
__device__ __forceinline__ unsigned f2tf(float f) {
  unsigned u;
  asm("cvt.rna.tf32.f32 %0, %1;" : "=r"(u) : "f"(f));
  return u;
}

__device__ __forceinline__ void mma8(float* c, const unsigned* a, const unsigned* b) {
  asm volatile(
      "mma.sync.aligned.m16n8k8.row.col.f32.tf32.tf32.f32 "
      "{%0,%1,%2,%3},{%4,%5,%6,%7},{%8,%9},{%0,%1,%2,%3};"
      : "+f"(c[0]), "+f"(c[1]), "+f"(c[2]), "+f"(c[3])
      : "r"(a[0]), "r"(a[1]), "r"(a[2]), "r"(a[3]), "r"(b[0]), "r"(b[1]));
}

// ---------------------------------------------------------------------------
// tf32 tensor-core GEMM: Out[m,n] (op)= sum_k In[m,k]*W[n,k] + bias[n]
// Block 128x128, Ktile 32, 256 threads (8 warps: 2M x 4N), warp tile 64x32.
// MODE 0: write; 1: GELU; 2: residual add. M%128==0, N%128==0, K%32==0, K%4==0.
// ---------------------------------------------------------------------------
template <int MODE>
__global__ __launch_bounds__(256) void gemm_tf32(
    const float* __restrict__ In, int ldIn,
    const float* __restrict__ W,       // [N][K] row-major
    const float* __restrict__ bias,    // [N] or nullptr
    float* __restrict__ Out, int ldOut, int K) {
  __shared__ unsigned As[32][136];  // [k][m], pad 8 -> bank = 8k+m (conflict-free quads)
  __shared__ unsigned Bs[32][136];  // [k][n]

  const int tid = threadIdx.x;
  const int lane = tid & 31, warp = tid >> 5;
  const int wm = warp & 1, wn = warp >> 1;
  const int g = lane >> 2, q = lane & 3;
  const int m0 = blockIdx.y * 128, n0 = blockIdx.x * 128;
  const int lr = tid & 127, lc = (tid >> 7) * 16;

  float acc[4][4][4];
#pragma unroll
  for (int mb = 0; mb < 4; mb++)
#pragma unroll
    for (int nb = 0; nb < 4; nb++)
#pragma unroll
      for (int r = 0; r < 4; r++) acc[mb][nb][r] = 0.f;

  const float* ap = In + (size_t)(m0 + lr) * ldIn + lc;
  const float* bp = W + (size_t)(n0 + lr) * K + lc;

  for (int kt = 0; kt < K; kt += 32) {
#pragma unroll
    for (int j = 0; j < 4; j++) {
      float4 av = *(const float4*)(ap + kt + j * 4);
      As[lc + j * 4 + 0][lr] = f2tf(av.x);
      As[lc + j * 4 + 1][lr] = f2tf(av.y);
      As[lc + j * 4 + 2][lr] = f2tf(av.z);
      As[lc + j * 4 + 3][lr] = f2tf(av.w);
      float4 bv = *(const float4*)(bp + kt + j * 4);
      Bs[lc + j * 4 + 0][lr] = f2tf(bv.x);
      Bs[lc + j * 4 + 1][lr] = f2tf(bv.y);
      Bs[lc + j * 4 + 2][lr] = f2tf(bv.z);
      Bs[lc + j * 4 + 3][lr] = f2tf(bv.w);
    }
    __syncthreads();
#pragma unroll
    for (int ks = 0; ks < 4; ks++) {
      const int k0 = ks * 8;
      unsigned a[4][4], b[4][2];
#pragma unroll
      for (int mb = 0; mb < 4; mb++) {
        int r = wm * 64 + mb * 16 + g;
        a[mb][0] = As[k0 + q][r];
        a[mb][1] = As[k0 + q][r + 8];
        a[mb][2] = As[k0 + q + 4][r];
        a[mb][3] = As[k0 + q + 4][r + 8];
      }
#pragma unroll
      for (int nb = 0; nb < 4; nb++) {
        int c = wn * 32 + nb * 8 + g;
        b[nb][0] = Bs[k0 + q][c];
        b[nb][1] = Bs[k0 + q + 4][c];
      }
#pragma unroll
      for (int mb = 0; mb < 4; mb++)
#pragma unroll
        for (int nb = 0; nb < 4; nb++) mma8(acc[mb][nb], a[mb], b[nb]);
    }
    __syncthreads();
  }

#pragma unroll
  for (int mb = 0; mb < 4; mb++) {
#pragma unroll
    for (int nb = 0; nb < 4; nb++) {
      int row = m0 + wm * 64 + mb * 16 + g;
      int col = n0 + wn * 32 + nb * 8 + 2 * q;
      float b0v = bias ? bias[col] : 0.f;
      float b1v = bias ? bias[col + 1] : 0.f;
      float v00 = acc[mb][nb][0] + b0v, v01 = acc[mb][nb][1] + b1v;
      float v10 = acc[mb][nb][2] + b0v, v11 = acc[mb][nb][3] + b1v;
      float* p0 = Out + (size_t)row * ldOut + col;
      float* p1 = Out + (size_t)(row + 8) * ldOut + col;
      if (MODE == 1) {
        v00 = 0.5f * v00 * (1.f + erff(v00 * 0.7071067811865476f));
        v01 = 0.5f * v01 * (1.f + erff(v01 * 0.7071067811865476f));
        v10 = 0.5f * v10 * (1.f + erff(v10 * 0.7071067811865476f));
        v11 = 0.5f * v11 * (1.f + erff(v11 * 0.7071067811865476f));
      }
      if (MODE == 2) {
        float2 o0 = *(const float2*)p0;
        float2 o1 = *(const float2*)p1;
        v00 += o0.x; v01 += o0.y; v10 += o1.x; v11 += o1.y;
      }
      *(float2*)p0 = make_float2(v00, v01);
      *(float2*)p1 = make_float2(v10, v11);
    }
  }
}

// ---------------------------------------------------------------------------
// fp32 fallback GEMM (only for cond embed, K=438): tile 128x64, 8x4 micro.
// ---------------------------------------------------------------------------
__global__ __launch_bounds__(256) void gemm_f32(
    const float* __restrict__ In, int ldIn, const float* __restrict__ W,
    const float* __restrict__ bias, float* __restrict__ Out, int ldOut, int K) {
  __shared__ float As[16][132];
  __shared__ float Bs[16][68];
  const int tid = threadIdx.x;
  const int tx = tid & 15, ty = tid >> 4;
  const int m0 = blockIdx.y * 128, n0 = blockIdx.x * 64;
  const int lr = tid >> 2, lc = (tid & 3) * 4;
  float acc[8][4];
#pragma unroll
  for (int r = 0; r < 8; r++)
#pragma unroll
    for (int c = 0; c < 4; c++) acc[r][c] = 0.f;
  for (int kt = 0; kt < K; kt += 16) {
#pragma unroll
    for (int qq = 0; qq < 4; qq++) {
      int k = kt + lc + qq;
      float av0 = 0.f, av1 = 0.f, bv = 0.f;
      if (k < K) {
        av0 = In[(size_t)(m0 + lr) * ldIn + k];
        av1 = In[(size_t)(m0 + lr + 64) * ldIn + k];
        bv = W[(size_t)(n0 + lr) * K + k];
      }
      As[lc + qq][lr] = av0;
      As[lc + qq][lr + 64] = av1;
      Bs[lc + qq][lr] = bv;
    }
    __syncthreads();
#pragma unroll
    for (int kk = 0; kk < 16; kk++) {
      float4 t0 = *(const float4*)&As[kk][ty * 8];
      float4 t1 = *(const float4*)&As[kk][ty * 8 + 4];
      float4 t2 = *(const float4*)&Bs[kk][tx * 4];
      float a[8] = {t0.x, t0.y, t0.z, t0.w, t1.x, t1.y, t1.z, t1.w};
      float bb[4] = {t2.x, t2.y, t2.z, t2.w};
#pragma unroll
      for (int r = 0; r < 8; r++)
#pragma unroll
        for (int c = 0; c < 4; c++) acc[r][c] += a[r] * bb[c];
    }
    __syncthreads();
  }
  float bv[4];
#pragma unroll
  for (int c = 0; c < 4; c++) bv[c] = bias ? bias[n0 + tx * 4 + c] : 0.f;
#pragma unroll
  for (int r = 0; r < 8; r++) {
    float* op = Out + (size_t)(m0 + ty * 8 + r) * ldOut + n0 + tx * 4;
    float4 o = {acc[r][0] + bv[0], acc[r][1] + bv[1], acc[r][2] + bv[2], acc[r][3] + bv[3]};
    *(float4*)op = o;
  }
}

// ---------------------------------------------------------------------------
// LayerNorm
// ---------------------------------------------------------------------------
__global__ __launch_bounds__(256) void ln_kernel(
    const float* __restrict__ x, const float* __restrict__ w,
    const float* __restrict__ b, float* __restrict__ out) {
  const int row = blockIdx.x;
  const int tid = threadIdx.x;
  const float* xr = x + (size_t)row * Cc;
  float v0 = xr[tid], v1 = xr[tid + 256], v2 = xr[tid + 512];
  __shared__ float red[8];
  float s = v0 + v1 + v2;
#pragma unroll
  for (int o = 16; o > 0; o >>= 1) s += __shfl_xor_sync(0xffffffffu, s, o);
  if ((tid & 31) == 0) red[tid >> 5] = s;
  __syncthreads();
  float mean = (red[0] + red[1] + red[2] + red[3] + red[4] + red[5] + red[6] + red[7]) * (1.f / 768.f);
  float d0 = v0 - mean, d1 = v1 - mean, d2 = v2 - mean;
  float sq = d0 * d0 + d1 * d1 + d2 * d2;
  __syncthreads();
#pragma unroll
  for (int o = 16; o > 0; o >>= 1) sq += __shfl_xor_sync(0xffffffffu, sq, o);
  if ((tid & 31) == 0) red[tid >> 5] = sq;
  __syncthreads();
  float var = (red[0] + red[1] + red[2] + red[3] + red[4] + red[5] + red[6] + red[7]) * (1.f / 768.f);
  float inv = rsqrtf(var + 1e-5f);
  float* orow = out + (size_t)row * Cc;
  orow[tid] = d0 * inv * w[tid] + b[tid];
  orow[tid + 256] = d1 * inv * w[tid + 256] + b[tid + 256];
  orow[tid + 512] = d2 * inv * w[tid + 512] + b[tid + 512];
}

// ---------------------------------------------------------------------------
// Embed
// ---------------------------------------------------------------------------
__global__ __launch_bounds__(256) void embed_kernel(
    const int* __restrict__ iu, const int* __restrict__ idn,
    const float* __restrict__ tu, const float* __restrict__ td,
    const float* __restrict__ pos, float* __restrict__ x) {
  int gidx = blockIdx.x * 256 + threadIdx.x;
  int c = gidx % Cc;
  int row = gidx / Cc;
  int i = row % Tt;
  int b = row / Tt;
  float p = pos[i * Cc + c];
  if (i < tt) x[gidx] += p;
  else if (i < 2 * tt) x[gidx] = tu[(size_t)iu[b * tt + (i - tt)] * Cc + c] + p;
  else x[gidx] = td[(size_t)idn[b * tt + (i - 2 * tt)] * Cc + c] + p;
}

// ---------------------------------------------------------------------------
// tf32 flash attention: block = (qtile 64, head, batch), 128 threads (4 warps).
// Warp w owns S/O rows 16w..16w+15. Dynamic smem:
//   Qt[64][72] (d-major), Kt[64][72] (d-major), Vs[64][73] (j-major), Ps[64][72] (j-major)
// ---------------------------------------------------------------------------
__global__ __launch_bounds__(128) void attn_tf32(
    const float* __restrict__ qkv, float* __restrict__ y) {
  extern __shared__ unsigned smx[];
  unsigned (*Qt)[72] = (unsigned(*)[72])smx;
  unsigned (*Kt)[72] = (unsigned(*)[72])(smx + 64 * 72);
  unsigned (*Vs)[73] = (unsigned(*)[73])(smx + 2 * 64 * 72);
  unsigned (*Ps)[72] = (unsigned(*)[72])(smx + 2 * 64 * 72 + 64 * 73);

  const int qt = blockIdx.x, h = blockIdx.y, b = blockIdx.z;
  const int tid = threadIdx.x, lane = tid & 31, warp = tid >> 5;
  const int g = lane >> 2, q = lane & 3;

  // Load Q tile, transposed to [d][i]
  {
    int i = tid & 63, ds = (tid >> 6) * 32;
    const float* qr = qkv + (size_t)(b * Tt + qt * 64 + i) * 2304 + h * 64 + ds;
#pragma unroll
    for (int j = 0; j < 8; j++) {
      float4 v = *(const float4*)(qr + j * 4);
      Qt[ds + j * 4 + 0][i] = f2tf(v.x);
      Qt[ds + j * 4 + 1][i] = f2tf(v.y);
      Qt[ds + j * 4 + 2][i] = f2tf(v.z);
      Qt[ds + j * 4 + 3][i] = f2tf(v.w);
    }
  }

  float m0r = -1e30f, m1r = -1e30f, l0 = 0.f, l1 = 0.f;
  float accO[8][4];
#pragma unroll
  for (int nb = 0; nb < 8; nb++)
#pragma unroll
    for (int r = 0; r < 4; r++) accO[nb][r] = 0.f;

  const int a = qt & 3;
  const int r0 = warp * 16 + g, r1 = r0 + 8;

  for (int kt = 0; kt < 12; kt++) {
    if ((kt & 3) > a) continue;
    const bool diag = ((kt & 3) == a);
    __syncthreads();
    {
      int j = tid & 63, ds = (tid >> 6) * 32;
      const float* kr = qkv + (size_t)(b * Tt + kt * 64 + j) * 2304 + 768 + h * 64 + ds;
      const float* vr = kr + 768;
#pragma unroll
      for (int jj = 0; jj < 8; jj++) {
        float4 kv = *(const float4*)(kr + jj * 4);
        Kt[ds + jj * 4 + 0][j] = f2tf(kv.x);
        Kt[ds + jj * 4 + 1][j] = f2tf(kv.y);
        Kt[ds + jj * 4 + 2][j] = f2tf(kv.z);
        Kt[ds + jj * 4 + 3][j] = f2tf(kv.w);
        float4 vv = *(const float4*)(vr + jj * 4);
        Vs[j][ds + jj * 4 + 0] = f2tf(vv.x);
        Vs[j][ds + jj * 4 + 1] = f2tf(vv.y);
        Vs[j][ds + jj * 4 + 2] = f2tf(vv.z);
        Vs[j][ds + jj * 4 + 3] = f2tf(vv.w);
      }
    }
    __syncthreads();

    // S = Q K^T
    float s[8][4];
#pragma unroll
    for (int nb = 0; nb < 8; nb++)
#pragma unroll
      for (int r = 0; r < 4; r++) s[nb][r] = 0.f;
#pragma unroll
    for (int ks = 0; ks < 8; ks++) {
      const int k0 = ks * 8;
      unsigned aa[4] = {Qt[k0 + q][r0], Qt[k0 + q][r1], Qt[k0 + q + 4][r0], Qt[k0 + q + 4][r1]};
#pragma unroll
      for (int nb = 0; nb < 8; nb++) {
        unsigned bb[2] = {Kt[k0 + q][nb * 8 + g], Kt[k0 + q + 4][nb * 8 + g]};
        mma8(s[nb], aa, bb);
      }
    }

    // scale + mask + rowmax
    float mx0 = -1e30f, mx1 = -1e30f;
#pragma unroll
    for (int nb = 0; nb < 8; nb++) {
      int c0 = nb * 8 + 2 * q;
      float v00 = s[nb][0] * 0.125f, v01 = s[nb][1] * 0.125f;
      float v10 = s[nb][2] * 0.125f, v11 = s[nb][3] * 0.125f;
      if (diag) {
        if (c0 > r0) v00 = -1e30f;
        if (c0 + 1 > r0) v01 = -1e30f;
        if (c0 > r1) v10 = -1e30f;
        if (c0 + 1 > r1) v11 = -1e30f;
      }
      s[nb][0] = v00; s[nb][1] = v01; s[nb][2] = v10; s[nb][3] = v11;
      mx0 = fmaxf(mx0, fmaxf(v00, v01));
      mx1 = fmaxf(mx1, fmaxf(v10, v11));
    }
    mx0 = fmaxf(mx0, __shfl_xor_sync(0xffffffffu, mx0, 1));
    mx0 = fmaxf(mx0, __shfl_xor_sync(0xffffffffu, mx0, 2));
    mx1 = fmaxf(mx1, __shfl_xor_sync(0xffffffffu, mx1, 1));
    mx1 = fmaxf(mx1, __shfl_xor_sync(0xffffffffu, mx1, 2));

    float mn0 = fmaxf(m0r, mx0), mn1 = fmaxf(m1r, mx1);
    float cf0 = __expf(m0r - mn0), cf1 = __expf(m1r - mn1);
    m0r = mn0; m1r = mn1;

    float rs0 = 0.f, rs1 = 0.f;
#pragma unroll
    for (int nb = 0; nb < 8; nb++) {
      int c0 = nb * 8 + 2 * q;
      float p00 = __expf(s[nb][0] - mn0);
      float p01 = __expf(s[nb][1] - mn0);
      float p10 = __expf(s[nb][2] - mn1);
      float p11 = __expf(s[nb][3] - mn1);
      rs0 += p00 + p01;
      rs1 += p10 + p11;
      Ps[c0][r0] = f2tf(p00);
      Ps[c0 + 1][r0] = f2tf(p01);
      Ps[c0][r1] = f2tf(p10);
      Ps[c0 + 1][r1] = f2tf(p11);
    }
    rs0 += __shfl_xor_sync(0xffffffffu, rs0, 1);
    rs0 += __shfl_xor_sync(0xffffffffu, rs0, 2);
    rs1 += __shfl_xor_sync(0xffffffffu, rs1, 1);
    rs1 += __shfl_xor_sync(0xffffffffu, rs1, 2);
    l0 = l0 * cf0 + rs0;
    l1 = l1 * cf1 + rs1;
#pragma unroll
    for (int nb = 0; nb < 8; nb++) {
      accO[nb][0] *= cf0; accO[nb][1] *= cf0;
      accO[nb][2] *= cf1; accO[nb][3] *= cf1;
    }
    __syncthreads();

    // O += P V
#pragma unroll
    for (int ks = 0; ks < 8; ks++) {
      const int k0 = ks * 8;
      unsigned aa[4] = {Ps[k0 + q][r0], Ps[k0 + q][r1], Ps[k0 + q + 4][r0], Ps[k0 + q + 4][r1]};
#pragma unroll
      for (int nb = 0; nb < 8; nb++) {
        unsigned bb[2] = {Vs[k0 + q][nb * 8 + g], Vs[k0 + q + 4][nb * 8 + g]};
        mma8(accO[nb], aa, bb);
      }
    }
  }

  // Epilogue
  float inv0 = 1.f / l0, inv1 = 1.f / l1;
#pragma unroll
  for (int nb = 0; nb < 8; nb++) {
    int c0 = nb * 8 + 2 * q;
    float* y0 = y + (size_t)(b * Tt + qt * 64 + r0) * Cc + h * 64 + c0;
    *(float2*)y0 = make_float2(accO[nb][0] * inv0, accO[nb][1] * inv0);
    *(float2*)(y0 + 8 * Cc) = make_float2(accO[nb][2] * inv1, accO[nb][3] * inv1);
  }
}

// ---------------------------------------------------------------------------
// Launcher
// ---------------------------------------------------------------------------
extern "C" void kernel_launch(void* const* d_in, const int* in_sizes, int n_in,
                              void* d_out, int out_size) {
  const int* idx_up = nullptr; const int* idx_down = nullptr;
  const float *cond = 0, *tok_up = 0, *tok_down = 0, *pos = 0, *cond_w = 0, *cond_b = 0;
  const float *lnf_w = 0, *lnf_b = 0, *hup = 0, *hdn = 0;
  const float *ln1[2] = {0, 0}, *ln2[2] = {0, 0}, *qkvw[2] = {0, 0}, *qkvb[2] = {0, 0};
  const float *projw[2] = {0, 0}, *projb[2] = {0, 0};
  const float *fc1w[2] = {0, 0}, *fc1b[2] = {0, 0}, *fc2w[2] = {0, 0}, *fc2b[2] = {0, 0};

  int c512 = 0, c393 = 0, c768 = 0, c9216 = 0, cqw = 0, cqb = 0, cpw = 0, c4608 = 0,
      cfw = 0, cfb = 0;
  for (int i = 0; i < n_in; i++) {
    const float* f = (const float*)d_in[i];
    switch (in_sizes[i]) {
      case 512:       if (c512 == 0) idx_up = (const int*)f; else idx_down = (const int*)f; c512++; break;
      case 224256:    cond = f; break;
      case 393216:    if (c393 == 0) tok_up = f; else if (c393 == 1) tok_down = f;
                      else if (c393 == 2) hup = f; else hdn = f; c393++; break;
      case 589824:    pos = f; break;
      case 336384:    cond_w = f; break;
      case 768:       if (c768 == 0) cond_b = f; else if (c768 == 1) lnf_w = f; else lnf_b = f; c768++; break;
      case 9216:      if (c9216 == 0) ln1[0] = f; else if (c9216 == 1) ln2[0] = f;
                      else if (c9216 == 2) ln1[1] = f; else ln2[1] = f; c9216++; break;
      case 10616832:  qkvw[cqw++] = f; break;
      case 13824:     qkvb[cqb++] = f; break;
      case 3538944:   projw[cpw++] = f; break;
      case 4608:      if (c4608 == 0) projb[0] = f; else if (c4608 == 1) fc2b[0] = f;
                      else if (c4608 == 2) projb[1] = f; else fc2b[1] = f; c4608++; break;
      case 14155776:  if (cfw == 0) fc1w[0] = f; else if (cfw == 1) fc2w[0] = f;
                      else if (cfw == 2) fc1w[1] = f; else fc2w[1] = f; cfw++; break;
      case 18432:     fc1b[cfb++] = f; break;
      default: break;
    }
  }

  float *x, *h, *y, *big;
  cudaGetSymbolAddress((void**)&x, g_x);
  cudaGetSymbolAddress((void**)&h, g_h);
  cudaGetSymbolAddress((void**)&y, g_y);
  cudaGetSymbolAddress((void**)&big, g_big);

  static const int ATTN_SMEM = (2 * 64 * 72 + 64 * 73 + 64 * 72) * 4;  // 73984
  cudaFuncSetAttribute(attn_tf32, cudaFuncAttributeMaxDynamicSharedMemorySize, ATTN_SMEM);

  // --- Embed ---
  for (int b = 0; b < Bz; b++)
    gemm_f32<<<dim3(Cc / 64, tt / 128), 256>>>(
        cond + (size_t)b * tt * 438, 438, cond_w, cond_b, x + (size_t)b * Tt * Cc, Cc, 438);
  embed_kernel<<<(Bz * Tt * Cc) / 256, 256>>>(idx_up, idx_down, tok_up, tok_down, pos, x);

  // --- 2 stacks x 6 blocks ---
  for (int st = 0; st < 2; st++) {
    for (int l = 0; l < 6; l++) {
      const float* w1 = ln1[st] + (size_t)l * 2 * Cc;
      ln_kernel<<<Bz * Tt, 256>>>(x, w1, w1 + Cc, h);
      gemm_tf32<0><<<dim3(3 * Cc / 128, Bz * Tt / 128), 256>>>(
          h, Cc, qkvw[st] + (size_t)l * 3 * Cc * Cc, qkvb[st] + (size_t)l * 3 * Cc,
          big, 3 * Cc, Cc);
      attn_tf32<<<dim3(Tt / 64, Hh, Bz), 128, ATTN_SMEM>>>(big, y);
      gemm_tf32<2><<<dim3(Cc / 128, Bz * Tt / 128), 256>>>(
          y, Cc, projw[st] + (size_t)l * Cc * Cc, projb[st] + (size_t)l * Cc, x, Cc, Cc);
      const float* w2 = ln2[st] + (size_t)l * 2 * Cc;
      ln_kernel<<<Bz * Tt, 256>>>(x, w2, w2 + Cc, h);
      gemm_tf32<1><<<dim3(FC / 128, Bz * Tt / 128), 256>>>(
          h, Cc, fc1w[st] + (size_t)l * FC * Cc, fc1b[st] + (size_t)l * FC, big, FC, Cc);
      gemm_tf32<2><<<dim3(Cc / 128, Bz * Tt / 128), 256>>>(
          big, FC, fc2w[st] + (size_t)l * Cc * FC, fc2b[st] + (size_t)l * Cc, x, Cc, FC);
    }
  }

  // --- Final LN + heads ---
  ln_kernel<<<Bz * Tt, 256>>>(x, lnf_w, lnf_b, h);
  float* out = (float*)d_out;
  for (int b = 0; b < Bz; b++) {
    gemm_tf32<0><<<dim3(Vv / 128, tt / 128), 256>>>(
        h + (size_t)(b * Tt + tt) * Cc, Cc, hup, nullptr, out + (size_t)b * tt * Vv, Vv, Cc);
    gemm_tf32<0><<<dim3(Vv / 128, tt / 128), 256>>>(
        h + (size_t)(b * Tt + 2 * tt) * Cc, Cc, hdn, nullptr,
        out + (size_t)(Bz * tt * Vv) + (size_t)b * tt * Vv, Vv, Cc);
  }
  (void)out_size; (void)n_in;
}

// round 3
// speedup vs baseline: 1.6652x; 1.2023x over previous
#include <cuda_runtime.h>
#include <math.h>

// Shapes
#define Bz 2
#define Tt 768
#define tt 256
#define Cc 768
#define Hh 12
#define FC 3072
#define Vv 512

// Scratch (allocation-free: __device__ globals)
__device__ float g_x[Bz * Tt * Cc];
__device__ float g_h[Bz * Tt * Cc];
__device__ float g_y[Bz * Tt * Cc];
__device__ float g_big[Bz * Tt * FC];

// ---------------------------------------------------------------------------
// tf32 helpers
// ---------------------------------------------------------------------------
__device__ __forceinline__ unsigned f2tf(float f) {
  unsigned u;
  asm("cvt.rna.tf32.f32 %0, %1;" : "=r"(u) : "f"(f));
  return u;
}

__device__ __forceinline__ void mma8(float* c, const unsigned* a, const unsigned* b) {
  asm volatile(
      "mma.sync.aligned.m16n8k8.row.col.f32.tf32.tf32.f32 "
      "{%0,%1,%2,%3},{%4,%5,%6,%7},{%8,%9},{%0,%1,%2,%3};"
      : "+f"(c[0]), "+f"(c[1]), "+f"(c[2]), "+f"(c[3])
      : "r"(a[0]), "r"(a[1]), "r"(a[2]), "r"(a[3]), "r"(b[0]), "r"(b[1]));
}

// ---------------------------------------------------------------------------
// Double-buffered tf32 GEMM: Out[m,n] (op)= sum_k In[m,k]*W[n,k] + bias[n]
// Block BM x 128, Ktile 32, 256 threads (8 warps: 2M x 4N), warp (BM/2)x32.
// Smem row-major [row][36] (pad 4): STS.128 conflict-free per phase,
// fragment LDS bank = (4g+q) distinct within warp.
// MODE 0: write; 1: GELU; 2: residual add. Requires M%BM==0, N%128==0, K%32==0.
// Dynamic smem: (2*BM*36 + 2*128*36)*4 bytes.
// ---------------------------------------------------------------------------
template <int BM, int MODE>
__global__ __launch_bounds__(256, 2) void gemm_tf32(
    const float* __restrict__ In, int ldIn,
    const float* __restrict__ W,       // [N][K] row-major
    const float* __restrict__ bias,    // [N] or nullptr
    float* __restrict__ Out, int ldOut, int K) {
  extern __shared__ unsigned sm[];
  unsigned* As = sm;                  // [2][BM][36]
  unsigned* Bs = sm + 2 * BM * 36;    // [2][128][36]

  constexpr int MB = BM / 32;         // m-frags per warp (4 or 2)
  constexpr int AV = BM / 32;         // float4 per thread for A stage

  const int tid = threadIdx.x;
  const int lane = tid & 31, warp = tid >> 5;
  const int wm = warp & 1, wn = warp >> 1;
  const int g = lane >> 2, q = lane & 3;
  const int m0 = blockIdx.y * BM, n0 = blockIdx.x * 128;

  // A stage mapping
  const int arow = tid & (BM - 1);
  const int acol = (tid / BM) * (AV * 4);
  // B stage mapping
  const int brow = tid & 127;
  const int bcol = (tid >> 7) * 16;

  const float* ap = In + (size_t)(m0 + arow) * ldIn + acol;
  const float* bp = W + (size_t)(n0 + brow) * K + bcol;

  float acc[MB][4][4];
#pragma unroll
  for (int mb = 0; mb < MB; mb++)
#pragma unroll
    for (int nb = 0; nb < 4; nb++)
#pragma unroll
      for (int r = 0; r < 4; r++) acc[mb][nb][r] = 0.f;

  float4 ra[AV], rb[4];

  // prolog: load + store tile 0
#pragma unroll
  for (int j = 0; j < AV; j++) ra[j] = *(const float4*)(ap + j * 4);
#pragma unroll
  for (int j = 0; j < 4; j++) rb[j] = *(const float4*)(bp + j * 4);
  {
    unsigned* a0 = As + arow * 36 + acol;
    unsigned* b0 = Bs + brow * 36 + bcol;
#pragma unroll
    for (int j = 0; j < AV; j++) {
      uint4 u = {f2tf(ra[j].x), f2tf(ra[j].y), f2tf(ra[j].z), f2tf(ra[j].w)};
      *(uint4*)(a0 + j * 4) = u;
    }
#pragma unroll
    for (int j = 0; j < 4; j++) {
      uint4 u = {f2tf(rb[j].x), f2tf(rb[j].y), f2tf(rb[j].z), f2tf(rb[j].w)};
      *(uint4*)(b0 + j * 4) = u;
    }
  }

  const int NT = K / 32;
  int cur = 0;
  for (int t = 0; t < NT; t++) {
    __syncthreads();
    if (t + 1 < NT) {
#pragma unroll
      for (int j = 0; j < AV; j++) ra[j] = *(const float4*)(ap + (t + 1) * 32 + j * 4);
#pragma unroll
      for (int j = 0; j < 4; j++) rb[j] = *(const float4*)(bp + (t + 1) * 32 + j * 4);
    }
    const unsigned* Ab = As + cur * BM * 36;
    const unsigned* Bb = Bs + cur * 128 * 36;
#pragma unroll
    for (int ks = 0; ks < 4; ks++) {
      const int k0 = ks * 8;
      unsigned a[MB][4], b[4][2];
#pragma unroll
      for (int mb = 0; mb < MB; mb++) {
        int r = wm * (BM / 2) + mb * 16 + g;
        a[mb][0] = Ab[r * 36 + k0 + q];
        a[mb][1] = Ab[(r + 8) * 36 + k0 + q];
        a[mb][2] = Ab[r * 36 + k0 + q + 4];
        a[mb][3] = Ab[(r + 8) * 36 + k0 + q + 4];
      }
#pragma unroll
      for (int nb = 0; nb < 4; nb++) {
        int c = wn * 32 + nb * 8 + g;
        b[nb][0] = Bb[c * 36 + k0 + q];
        b[nb][1] = Bb[c * 36 + k0 + q + 4];
      }
#pragma unroll
      for (int mb = 0; mb < MB; mb++)
#pragma unroll
        for (int nb = 0; nb < 4; nb++) mma8(acc[mb][nb], a[mb], b[nb]);
    }
    if (t + 1 < NT) {
      unsigned* a0 = As + (1 - cur) * BM * 36 + arow * 36 + acol;
      unsigned* b0 = Bs + (1 - cur) * 128 * 36 + brow * 36 + bcol;
#pragma unroll
      for (int j = 0; j < AV; j++) {
        uint4 u = {f2tf(ra[j].x), f2tf(ra[j].y), f2tf(ra[j].z), f2tf(ra[j].w)};
        *(uint4*)(a0 + j * 4) = u;
      }
#pragma unroll
      for (int j = 0; j < 4; j++) {
        uint4 u = {f2tf(rb[j].x), f2tf(rb[j].y), f2tf(rb[j].z), f2tf(rb[j].w)};
        *(uint4*)(b0 + j * 4) = u;
      }
    }
    cur ^= 1;
  }

  // epilogue
#pragma unroll
  for (int mb = 0; mb < MB; mb++) {
#pragma unroll
    for (int nb = 0; nb < 4; nb++) {
      int row = m0 + wm * (BM / 2) + mb * 16 + g;
      int col = n0 + wn * 32 + nb * 8 + 2 * q;
      float b0v = bias ? bias[col] : 0.f;
      float b1v = bias ? bias[col + 1] : 0.f;
      float v00 = acc[mb][nb][0] + b0v, v01 = acc[mb][nb][1] + b1v;
      float v10 = acc[mb][nb][2] + b0v, v11 = acc[mb][nb][3] + b1v;
      float* p0 = Out + (size_t)row * ldOut + col;
      float* p1 = Out + (size_t)(row + 8) * ldOut + col;
      if (MODE == 1) {
        v00 = 0.5f * v00 * (1.f + erff(v00 * 0.7071067811865476f));
        v01 = 0.5f * v01 * (1.f + erff(v01 * 0.7071067811865476f));
        v10 = 0.5f * v10 * (1.f + erff(v10 * 0.7071067811865476f));
        v11 = 0.5f * v11 * (1.f + erff(v11 * 0.7071067811865476f));
      }
      if (MODE == 2) {
        float2 o0 = *(const float2*)p0;
        float2 o1 = *(const float2*)p1;
        v00 += o0.x; v01 += o0.y; v10 += o1.x; v11 += o1.y;
      }
      *(float2*)p0 = make_float2(v00, v01);
      *(float2*)p1 = make_float2(v10, v11);
    }
  }
}

// ---------------------------------------------------------------------------
// fp32 fallback GEMM (only for cond embed, K=438): tile 128x64, 8x4 micro.
// ---------------------------------------------------------------------------
__global__ __launch_bounds__(256) void gemm_f32(
    const float* __restrict__ In, int ldIn, const float* __restrict__ W,
    const float* __restrict__ bias, float* __restrict__ Out, int ldOut, int K) {
  __shared__ float As[16][132];
  __shared__ float Bs[16][68];
  const int tid = threadIdx.x;
  const int tx = tid & 15, ty = tid >> 4;
  const int m0 = blockIdx.y * 128, n0 = blockIdx.x * 64;
  const int lr = tid >> 2, lc = (tid & 3) * 4;
  float acc[8][4];
#pragma unroll
  for (int r = 0; r < 8; r++)
#pragma unroll
    for (int c = 0; c < 4; c++) acc[r][c] = 0.f;
  for (int kt = 0; kt < K; kt += 16) {
#pragma unroll
    for (int qq = 0; qq < 4; qq++) {
      int k = kt + lc + qq;
      float av0 = 0.f, av1 = 0.f, bv = 0.f;
      if (k < K) {
        av0 = In[(size_t)(m0 + lr) * ldIn + k];
        av1 = In[(size_t)(m0 + lr + 64) * ldIn + k];
        bv = W[(size_t)(n0 + lr) * K + k];
      }
      As[lc + qq][lr] = av0;
      As[lc + qq][lr + 64] = av1;
      Bs[lc + qq][lr] = bv;
    }
    __syncthreads();
#pragma unroll
    for (int kk = 0; kk < 16; kk++) {
      float4 t0 = *(const float4*)&As[kk][ty * 8];
      float4 t1 = *(const float4*)&As[kk][ty * 8 + 4];
      float4 t2 = *(const float4*)&Bs[kk][tx * 4];
      float a[8] = {t0.x, t0.y, t0.z, t0.w, t1.x, t1.y, t1.z, t1.w};
      float bb[4] = {t2.x, t2.y, t2.z, t2.w};
#pragma unroll
      for (int r = 0; r < 8; r++)
#pragma unroll
        for (int c = 0; c < 4; c++) acc[r][c] += a[r] * bb[c];
    }
    __syncthreads();
  }
  float bv[4];
#pragma unroll
  for (int c = 0; c < 4; c++) bv[c] = bias ? bias[n0 + tx * 4 + c] : 0.f;
#pragma unroll
  for (int r = 0; r < 8; r++) {
    float* op = Out + (size_t)(m0 + ty * 8 + r) * ldOut + n0 + tx * 4;
    float4 o = {acc[r][0] + bv[0], acc[r][1] + bv[1], acc[r][2] + bv[2], acc[r][3] + bv[3]};
    *(float4*)op = o;
  }
}

// ---------------------------------------------------------------------------
// LayerNorm
// ---------------------------------------------------------------------------
__global__ __launch_bounds__(256) void ln_kernel(
    const float* __restrict__ x, const float* __restrict__ w,
    const float* __restrict__ b, float* __restrict__ out) {
  const int row = blockIdx.x;
  const int tid = threadIdx.x;
  const float* xr = x + (size_t)row * Cc;
  float v0 = xr[tid], v1 = xr[tid + 256], v2 = xr[tid + 512];
  __shared__ float red[8];
  float s = v0 + v1 + v2;
#pragma unroll
  for (int o = 16; o > 0; o >>= 1) s += __shfl_xor_sync(0xffffffffu, s, o);
  if ((tid & 31) == 0) red[tid >> 5] = s;
  __syncthreads();
  float mean = (red[0] + red[1] + red[2] + red[3] + red[4] + red[5] + red[6] + red[7]) * (1.f / 768.f);
  float d0 = v0 - mean, d1 = v1 - mean, d2 = v2 - mean;
  float sq = d0 * d0 + d1 * d1 + d2 * d2;
  __syncthreads();
#pragma unroll
  for (int o = 16; o > 0; o >>= 1) sq += __shfl_xor_sync(0xffffffffu, sq, o);
  if ((tid & 31) == 0) red[tid >> 5] = sq;
  __syncthreads();
  float var = (red[0] + red[1] + red[2] + red[3] + red[4] + red[5] + red[6] + red[7]) * (1.f / 768.f);
  float inv = rsqrtf(var + 1e-5f);
  float* orow = out + (size_t)row * Cc;
  orow[tid] = d0 * inv * w[tid] + b[tid];
  orow[tid + 256] = d1 * inv * w[tid + 256] + b[tid + 256];
  orow[tid + 512] = d2 * inv * w[tid + 512] + b[tid + 512];
}

// ---------------------------------------------------------------------------
// Embed
// ---------------------------------------------------------------------------
__global__ __launch_bounds__(256) void embed_kernel(
    const int* __restrict__ iu, const int* __restrict__ idn,
    const float* __restrict__ tu, const float* __restrict__ td,
    const float* __restrict__ pos, float* __restrict__ x) {
  int gidx = blockIdx.x * 256 + threadIdx.x;
  int c = gidx % Cc;
  int row = gidx / Cc;
  int i = row % Tt;
  int b = row / Tt;
  float p = pos[i * Cc + c];
  if (i < tt) x[gidx] += p;
  else if (i < 2 * tt) x[gidx] = tu[(size_t)iu[b * tt + (i - tt)] * Cc + c] + p;
  else x[gidx] = td[(size_t)idn[b * tt + (i - 2 * tt)] * Cc + c] + p;
}

// ---------------------------------------------------------------------------
// tf32 flash attention (unchanged from round 2)
// ---------------------------------------------------------------------------
__global__ __launch_bounds__(128) void attn_tf32(
    const float* __restrict__ qkv, float* __restrict__ y) {
  extern __shared__ unsigned smx[];
  unsigned (*Qt)[72] = (unsigned(*)[72])smx;
  unsigned (*Kt)[72] = (unsigned(*)[72])(smx + 64 * 72);
  unsigned (*Vs)[73] = (unsigned(*)[73])(smx + 2 * 64 * 72);
  unsigned (*Ps)[72] = (unsigned(*)[72])(smx + 2 * 64 * 72 + 64 * 73);

  const int qt = blockIdx.x, h = blockIdx.y, b = blockIdx.z;
  const int tid = threadIdx.x, lane = tid & 31, warp = tid >> 5;
  const int g = lane >> 2, q = lane & 3;

  {
    int i = tid & 63, ds = (tid >> 6) * 32;
    const float* qr = qkv + (size_t)(b * Tt + qt * 64 + i) * 2304 + h * 64 + ds;
#pragma unroll
    for (int j = 0; j < 8; j++) {
      float4 v = *(const float4*)(qr + j * 4);
      Qt[ds + j * 4 + 0][i] = f2tf(v.x);
      Qt[ds + j * 4 + 1][i] = f2tf(v.y);
      Qt[ds + j * 4 + 2][i] = f2tf(v.z);
      Qt[ds + j * 4 + 3][i] = f2tf(v.w);
    }
  }

  float m0r = -1e30f, m1r = -1e30f, l0 = 0.f, l1 = 0.f;
  float accO[8][4];
#pragma unroll
  for (int nb = 0; nb < 8; nb++)
#pragma unroll
    for (int r = 0; r < 4; r++) accO[nb][r] = 0.f;

  const int a = qt & 3;
  const int r0 = warp * 16 + g, r1 = r0 + 8;

  for (int kt = 0; kt < 12; kt++) {
    if ((kt & 3) > a) continue;
    const bool diag = ((kt & 3) == a);
    __syncthreads();
    {
      int j = tid & 63, ds = (tid >> 6) * 32;
      const float* kr = qkv + (size_t)(b * Tt + kt * 64 + j) * 2304 + 768 + h * 64 + ds;
      const float* vr = kr + 768;
#pragma unroll
      for (int jj = 0; jj < 8; jj++) {
        float4 kv = *(const float4*)(kr + jj * 4);
        Kt[ds + jj * 4 + 0][j] = f2tf(kv.x);
        Kt[ds + jj * 4 + 1][j] = f2tf(kv.y);
        Kt[ds + jj * 4 + 2][j] = f2tf(kv.z);
        Kt[ds + jj * 4 + 3][j] = f2tf(kv.w);
        float4 vv = *(const float4*)(vr + jj * 4);
        Vs[j][ds + jj * 4 + 0] = f2tf(vv.x);
        Vs[j][ds + jj * 4 + 1] = f2tf(vv.y);
        Vs[j][ds + jj * 4 + 2] = f2tf(vv.z);
        Vs[j][ds + jj * 4 + 3] = f2tf(vv.w);
      }
    }
    __syncthreads();

    float s[8][4];
#pragma unroll
    for (int nb = 0; nb < 8; nb++)
#pragma unroll
      for (int r = 0; r < 4; r++) s[nb][r] = 0.f;
#pragma unroll
    for (int ks = 0; ks < 8; ks++) {
      const int k0 = ks * 8;
      unsigned aa[4] = {Qt[k0 + q][r0], Qt[k0 + q][r1], Qt[k0 + q + 4][r0], Qt[k0 + q + 4][r1]};
#pragma unroll
      for (int nb = 0; nb < 8; nb++) {
        unsigned bb[2] = {Kt[k0 + q][nb * 8 + g], Kt[k0 + q + 4][nb * 8 + g]};
        mma8(s[nb], aa, bb);
      }
    }

    float mx0 = -1e30f, mx1 = -1e30f;
#pragma unroll
    for (int nb = 0; nb < 8; nb++) {
      int c0 = nb * 8 + 2 * q;
      float v00 = s[nb][0] * 0.125f, v01 = s[nb][1] * 0.125f;
      float v10 = s[nb][2] * 0.125f, v11 = s[nb][3] * 0.125f;
      if (diag) {
        if (c0 > r0) v00 = -1e30f;
        if (c0 + 1 > r0) v01 = -1e30f;
        if (c0 > r1) v10 = -1e30f;
        if (c0 + 1 > r1) v11 = -1e30f;
      }
      s[nb][0] = v00; s[nb][1] = v01; s[nb][2] = v10; s[nb][3] = v11;
      mx0 = fmaxf(mx0, fmaxf(v00, v01));
      mx1 = fmaxf(mx1, fmaxf(v10, v11));
    }
    mx0 = fmaxf(mx0, __shfl_xor_sync(0xffffffffu, mx0, 1));
    mx0 = fmaxf(mx0, __shfl_xor_sync(0xffffffffu, mx0, 2));
    mx1 = fmaxf(mx1, __shfl_xor_sync(0xffffffffu, mx1, 1));
    mx1 = fmaxf(mx1, __shfl_xor_sync(0xffffffffu, mx1, 2));

    float mn0 = fmaxf(m0r, mx0), mn1 = fmaxf(m1r, mx1);
    float cf0 = __expf(m0r - mn0), cf1 = __expf(m1r - mn1);
    m0r = mn0; m1r = mn1;

    float rs0 = 0.f, rs1 = 0.f;
#pragma unroll
    for (int nb = 0; nb < 8; nb++) {
      int c0 = nb * 8 + 2 * q;
      float p00 = __expf(s[nb][0] - mn0);
      float p01 = __expf(s[nb][1] - mn0);
      float p10 = __expf(s[nb][2] - mn1);
      float p11 = __expf(s[nb][3] - mn1);
      rs0 += p00 + p01;
      rs1 += p10 + p11;
      Ps[c0][r0] = f2tf(p00);
      Ps[c0 + 1][r0] = f2tf(p01);
      Ps[c0][r1] = f2tf(p10);
      Ps[c0 + 1][r1] = f2tf(p11);
    }
    rs0 += __shfl_xor_sync(0xffffffffu, rs0, 1);
    rs0 += __shfl_xor_sync(0xffffffffu, rs0, 2);
    rs1 += __shfl_xor_sync(0xffffffffu, rs1, 1);
    rs1 += __shfl_xor_sync(0xffffffffu, rs1, 2);
    l0 = l0 * cf0 + rs0;
    l1 = l1 * cf1 + rs1;
#pragma unroll
    for (int nb = 0; nb < 8; nb++) {
      accO[nb][0] *= cf0; accO[nb][1] *= cf0;
      accO[nb][2] *= cf1; accO[nb][3] *= cf1;
    }
    __syncthreads();

#pragma unroll
    for (int ks = 0; ks < 8; ks++) {
      const int k0 = ks * 8;
      unsigned aa[4] = {Ps[k0 + q][r0], Ps[k0 + q][r1], Ps[k0 + q + 4][r0], Ps[k0 + q + 4][r1]};
#pragma unroll
      for (int nb = 0; nb < 8; nb++) {
        unsigned bb[2] = {Vs[k0 + q][nb * 8 + g], Vs[k0 + q + 4][nb * 8 + g]};
        mma8(accO[nb], aa, bb);
      }
    }
  }

  float inv0 = 1.f / l0, inv1 = 1.f / l1;
#pragma unroll
  for (int nb = 0; nb < 8; nb++) {
    int c0 = nb * 8 + 2 * q;
    float* y0 = y + (size_t)(b * Tt + qt * 64 + r0) * Cc + h * 64 + c0;
    *(float2*)y0 = make_float2(accO[nb][0] * inv0, accO[nb][1] * inv0);
    *(float2*)(y0 + 8 * Cc) = make_float2(accO[nb][2] * inv1, accO[nb][3] * inv1);
  }
}

// ---------------------------------------------------------------------------
// Launcher
// ---------------------------------------------------------------------------
extern "C" void kernel_launch(void* const* d_in, const int* in_sizes, int n_in,
                              void* d_out, int out_size) {
  const int* idx_up = nullptr; const int* idx_down = nullptr;
  const float *cond = 0, *tok_up = 0, *tok_down = 0, *pos = 0, *cond_w = 0, *cond_b = 0;
  const float *lnf_w = 0, *lnf_b = 0, *hup = 0, *hdn = 0;
  const float *ln1[2] = {0, 0}, *ln2[2] = {0, 0}, *qkvw[2] = {0, 0}, *qkvb[2] = {0, 0};
  const float *projw[2] = {0, 0}, *projb[2] = {0, 0};
  const float *fc1w[2] = {0, 0}, *fc1b[2] = {0, 0}, *fc2w[2] = {0, 0}, *fc2b[2] = {0, 0};

  int c512 = 0, c393 = 0, c768 = 0, c9216 = 0, cqw = 0, cqb = 0, cpw = 0, c4608 = 0,
      cfw = 0, cfb = 0;
  for (int i = 0; i < n_in; i++) {
    const float* f = (const float*)d_in[i];
    switch (in_sizes[i]) {
      case 512:       if (c512 == 0) idx_up = (const int*)f; else idx_down = (const int*)f; c512++; break;
      case 224256:    cond = f; break;
      case 393216:    if (c393 == 0) tok_up = f; else if (c393 == 1) tok_down = f;
                      else if (c393 == 2) hup = f; else hdn = f; c393++; break;
      case 589824:    pos = f; break;
      case 336384:    cond_w = f; break;
      case 768:       if (c768 == 0) cond_b = f; else if (c768 == 1) lnf_w = f; else lnf_b = f; c768++; break;
      case 9216:      if (c9216 == 0) ln1[0] = f; else if (c9216 == 1) ln2[0] = f;
                      else if (c9216 == 2) ln1[1] = f; else ln2[1] = f; c9216++; break;
      case 10616832:  qkvw[cqw++] = f; break;
      case 13824:     qkvb[cqb++] = f; break;
      case 3538944:   projw[cpw++] = f; break;
      case 4608:      if (c4608 == 0) projb[0] = f; else if (c4608 == 1) fc2b[0] = f;
                      else if (c4608 == 2) projb[1] = f; else fc2b[1] = f; c4608++; break;
      case 14155776:  if (cfw == 0) fc1w[0] = f; else if (cfw == 1) fc2w[0] = f;
                      else if (cfw == 2) fc1w[1] = f; else fc2w[1] = f; cfw++; break;
      case 18432:     fc1b[cfb++] = f; break;
      default: break;
    }
  }

  float *x, *h, *y, *big;
  cudaGetSymbolAddress((void**)&x, g_x);
  cudaGetSymbolAddress((void**)&h, g_h);
  cudaGetSymbolAddress((void**)&y, g_y);
  cudaGetSymbolAddress((void**)&big, g_big);

  const int SM128 = (2 * 128 * 36 + 2 * 128 * 36) * 4;  // 73728
  const int SM64 = (2 * 64 * 36 + 2 * 128 * 36) * 4;    // 55296
  cudaFuncSetAttribute(gemm_tf32<128, 0>, cudaFuncAttributeMaxDynamicSharedMemorySize, SM128);
  cudaFuncSetAttribute(gemm_tf32<128, 1>, cudaFuncAttributeMaxDynamicSharedMemorySize, SM128);
  cudaFuncSetAttribute(gemm_tf32<64, 2>, cudaFuncAttributeMaxDynamicSharedMemorySize, SM64);
  cudaFuncSetAttribute(gemm_tf32<64, 0>, cudaFuncAttributeMaxDynamicSharedMemorySize, SM64);

  const int ATTN_SMEM = (2 * 64 * 72 + 64 * 73 + 64 * 72) * 4;  // 73984
  cudaFuncSetAttribute(attn_tf32, cudaFuncAttributeMaxDynamicSharedMemorySize, ATTN_SMEM);

  // --- Embed ---
  for (int b = 0; b < Bz; b++)
    gemm_f32<<<dim3(Cc / 64, tt / 128), 256>>>(
        cond + (size_t)b * tt * 438, 438, cond_w, cond_b, x + (size_t)b * Tt * Cc, Cc, 438);
  embed_kernel<<<(Bz * Tt * Cc) / 256, 256>>>(idx_up, idx_down, tok_up, tok_down, pos, x);

  // --- 2 stacks x 6 blocks ---
  for (int st = 0; st < 2; st++) {
    for (int l = 0; l < 6; l++) {
      const float* w1 = ln1[st] + (size_t)l * 2 * Cc;
      ln_kernel<<<Bz * Tt, 256>>>(x, w1, w1 + Cc, h);
      gemm_tf32<128, 0><<<dim3(3 * Cc / 128, Bz * Tt / 128), 256, SM128>>>(
          h, Cc, qkvw[st] + (size_t)l * 3 * Cc * Cc, qkvb[st] + (size_t)l * 3 * Cc,
          big, 3 * Cc, Cc);
      attn_tf32<<<dim3(Tt / 64, Hh, Bz), 128, ATTN_SMEM>>>(big, y);
      gemm_tf32<64, 2><<<dim3(Cc / 128, Bz * Tt / 64), 256, SM64>>>(
          y, Cc, projw[st] + (size_t)l * Cc * Cc, projb[st] + (size_t)l * Cc, x, Cc, Cc);
      const float* w2 = ln2[st] + (size_t)l * 2 * Cc;
      ln_kernel<<<Bz * Tt, 256>>>(x, w2, w2 + Cc, h);
      gemm_tf32<128, 1><<<dim3(FC / 128, Bz * Tt / 128), 256, SM128>>>(
          h, Cc, fc1w[st] + (size_t)l * FC * Cc, fc1b[st] + (size_t)l * FC, big, FC, Cc);
      gemm_tf32<64, 2><<<dim3(Cc / 128, Bz * Tt / 64), 256, SM64>>>(
          big, FC, fc2w[st] + (size_t)l * Cc * FC, fc2b[st] + (size_t)l * Cc, x, Cc, FC);
    }
  }

  // --- Final LN + heads ---
  ln_kernel<<<Bz * Tt, 256>>>(x, lnf_w, lnf_b, h);
  float* out = (float*)d_out;
  for (int b = 0; b < Bz; b++) {
    gemm_tf32<64, 0><<<dim3(Vv / 128, tt / 64), 256, SM64>>>(
        h + (size_t)(b * Tt + tt) * Cc, Cc, hup, nullptr, out + (size_t)b * tt * Vv, Vv, Cc);
    gemm_tf32<64, 0><<<dim3(Vv / 128, tt / 64), 256, SM64>>>(
        h + (size_t)(b * Tt + 2 * tt) * Cc, Cc, hdn, nullptr,
        out + (size_t)(Bz * tt * Vv) + (size_t)b * tt * Vv, Vv, Cc);
  }
  (void)out_size; (void)n_in;
}

// round 7
// speedup vs baseline: 1.9422x; 1.1663x over previous
#include <cuda_runtime.h>
#include <math.h>
#include <stdint.h>

// Shapes
#define Bz 2
#define Tt 768
#define tt 256
#define Cc 768
#define Hh 12
#define FC 3072
#define Vv 512

// Scratch (allocation-free: __device__ globals)
__device__ float g_x[Bz * Tt * Cc];
__device__ float g_h[Bz * Tt * Cc];
__device__ float g_y[Bz * Tt * Cc];
__device__ float g_big[Bz * Tt * FC];

// ---------------------------------------------------------------------------
// helpers
// ---------------------------------------------------------------------------
__device__ __forceinline__ unsigned f2tf(float f) {
  unsigned u;
  asm("cvt.rna.tf32.f32 %0, %1;" : "=r"(u) : "f"(f));
  return u;
}
// pack two fp32 -> half2 (lo = first arg)
__device__ __forceinline__ unsigned packh2(float lo, float hi) {
  unsigned u;
  asm("cvt.rn.f16x2.f32 %0, %1, %2;" : "=r"(u) : "f"(hi), "f"(lo));
  return u;
}

__device__ __forceinline__ void mma16h(float* c, const unsigned* a, const unsigned* b) {
  asm volatile(
      "mma.sync.aligned.m16n8k16.row.col.f32.f16.f16.f32 "
      "{%0,%1,%2,%3},{%4,%5,%6,%7},{%8,%9},{%0,%1,%2,%3};"
      : "+f"(c[0]), "+f"(c[1]), "+f"(c[2]), "+f"(c[3])
      : "r"(a[0]), "r"(a[1]), "r"(a[2]), "r"(a[3]), "r"(b[0]), "r"(b[1]));
}

__device__ __forceinline__ void mma8(float* c, const unsigned* a, const unsigned* b) {
  asm volatile(
      "mma.sync.aligned.m16n8k8.row.col.f32.tf32.tf32.f32 "
      "{%0,%1,%2,%3},{%4,%5,%6,%7},{%8,%9},{%0,%1,%2,%3};"
      : "+f"(c[0]), "+f"(c[1]), "+f"(c[2]), "+f"(c[3])
      : "r"(a[0]), "r"(a[1]), "r"(a[2]), "r"(a[3]), "r"(b[0]), "r"(b[1]));
}

// ---------------------------------------------------------------------------
// fp16 tensor-core GEMM (fp32 accum): Out[m,n] (op)= sum_k In[m,k]*W[n,k]+bias
// Block BM x 128, Ktile 32 (2 k16 MMA steps), 256 threads (8 warps: 2M x 4N),
// warp tile (BM/2) x 32. Smem half2 [row][20] (16 k-pairs + pad 4):
// fragment LDS banks 20g+q all-distinct. Double buffered.
// MODE 0: write; 1: GELU; 2: residual add. M%BM==0, N%128==0, K%32==0.
// ---------------------------------------------------------------------------
template <int BM, int MODE>
__global__ __launch_bounds__(256, 2) void gemm_h(
    const float* __restrict__ In, int ldIn,
    const float* __restrict__ W,       // [N][K] row-major
    const float* __restrict__ bias,    // [N] or nullptr
    float* __restrict__ Out, int ldOut, int K) {
  __shared__ unsigned As[2][BM][20];
  __shared__ unsigned Bs[2][128][20];

  constexpr int MB = BM / 32;   // m-frags per warp
  constexpr int AF4 = BM / 32;  // float4 per thread for A stage

  const int tid = threadIdx.x;
  const int lane = tid & 31, warp = tid >> 5;
  const int wm = warp & 1, wn = warp >> 1;
  const int g = lane >> 2, q = lane & 3;
  const int m0 = blockIdx.y * BM, n0 = blockIdx.x * 128;

  const int arow = tid & (BM - 1);
  const int acolf = (tid / BM) * (AF4 * 4);   // float offset in k
  const int brow = tid & 127;
  const int bcolf = (tid >> 7) * 16;

  const float* ap = In + (size_t)(m0 + arow) * ldIn + acolf;
  const float* bp = W + (size_t)(n0 + brow) * K + bcolf;

  float acc[MB][4][4];
#pragma unroll
  for (int mb = 0; mb < MB; mb++)
#pragma unroll
    for (int nb = 0; nb < 4; nb++)
#pragma unroll
      for (int r = 0; r < 4; r++) acc[mb][nb][r] = 0.f;

  float4 ra[AF4], rb[4];

  // prolog: tile 0
#pragma unroll
  for (int j = 0; j < AF4; j++) ra[j] = *(const float4*)(ap + j * 4);
#pragma unroll
  for (int j = 0; j < 4; j++) rb[j] = *(const float4*)(bp + j * 4);
  {
#pragma unroll
    for (int j = 0; j < AF4; j++) {
      uint2 u = {packh2(ra[j].x, ra[j].y), packh2(ra[j].z, ra[j].w)};
      *(uint2*)&As[0][arow][acolf / 2 + j * 2] = u;
    }
#pragma unroll
    for (int j = 0; j < 4; j++) {
      uint2 u = {packh2(rb[j].x, rb[j].y), packh2(rb[j].z, rb[j].w)};
      *(uint2*)&Bs[0][brow][bcolf / 2 + j * 2] = u;
    }
  }

  const int NT = K / 32;
  int cur = 0;
  for (int t = 0; t < NT; t++) {
    __syncthreads();
    if (t + 1 < NT) {
#pragma unroll
      for (int j = 0; j < AF4; j++) ra[j] = *(const float4*)(ap + (t + 1) * 32 + j * 4);
#pragma unroll
      for (int j = 0; j < 4; j++) rb[j] = *(const float4*)(bp + (t + 1) * 32 + j * 4);
    }
#pragma unroll
    for (int ks = 0; ks < 2; ks++) {
      const int k0 = ks * 8;
      unsigned a[MB][4], b[4][2];
#pragma unroll
      for (int mb = 0; mb < MB; mb++) {
        int r = wm * (BM / 2) + mb * 16 + g;
        a[mb][0] = As[cur][r][k0 + q];
        a[mb][1] = As[cur][r + 8][k0 + q];
        a[mb][2] = As[cur][r][k0 + q + 4];
        a[mb][3] = As[cur][r + 8][k0 + q + 4];
      }
#pragma unroll
      for (int nb = 0; nb < 4; nb++) {
        int c = wn * 32 + nb * 8 + g;
        b[nb][0] = Bs[cur][c][k0 + q];
        b[nb][1] = Bs[cur][c][k0 + q + 4];
      }
#pragma unroll
      for (int mb = 0; mb < MB; mb++)
#pragma unroll
        for (int nb = 0; nb < 4; nb++) mma16h(acc[mb][nb], a[mb], b[nb]);
    }
    if (t + 1 < NT) {
#pragma unroll
      for (int j = 0; j < AF4; j++) {
        uint2 u = {packh2(ra[j].x, ra[j].y), packh2(ra[j].z, ra[j].w)};
        *(uint2*)&As[1 - cur][arow][acolf / 2 + j * 2] = u;
      }
#pragma unroll
      for (int j = 0; j < 4; j++) {
        uint2 u = {packh2(rb[j].x, rb[j].y), packh2(rb[j].z, rb[j].w)};
        *(uint2*)&Bs[1 - cur][brow][bcolf / 2 + j * 2] = u;
      }
    }
    cur ^= 1;
  }

  // epilogue
#pragma unroll
  for (int mb = 0; mb < MB; mb++) {
#pragma unroll
    for (int nb = 0; nb < 4; nb++) {
      int row = m0 + wm * (BM / 2) + mb * 16 + g;
      int col = n0 + wn * 32 + nb * 8 + 2 * q;
      float b0v = bias ? bias[col] : 0.f;
      float b1v = bias ? bias[col + 1] : 0.f;
      float v00 = acc[mb][nb][0] + b0v, v01 = acc[mb][nb][1] + b1v;
      float v10 = acc[mb][nb][2] + b0v, v11 = acc[mb][nb][3] + b1v;
      float* p0 = Out + (size_t)row * ldOut + col;
      float* p1 = Out + (size_t)(row + 8) * ldOut + col;
      if (MODE == 1) {
        v00 = 0.5f * v00 * (1.f + erff(v00 * 0.7071067811865476f));
        v01 = 0.5f * v01 * (1.f + erff(v01 * 0.7071067811865476f));
        v10 = 0.5f * v10 * (1.f + erff(v10 * 0.7071067811865476f));
        v11 = 0.5f * v11 * (1.f + erff(v11 * 0.7071067811865476f));
      }
      if (MODE == 2) {
        float2 o0 = *(const float2*)p0;
        float2 o1 = *(const float2*)p1;
        v00 += o0.x; v01 += o0.y; v10 += o1.x; v11 += o1.y;
      }
      *(float2*)p0 = make_float2(v00, v01);
      *(float2*)p1 = make_float2(v10, v11);
    }
  }
}

// ---------------------------------------------------------------------------
// fp32 fallback GEMM (cond embed, K=438): tile 128x64, 8x4 micro.
// ---------------------------------------------------------------------------
__global__ __launch_bounds__(256) void gemm_f32(
    const float* __restrict__ In, int ldIn, const float* __restrict__ W,
    const float* __restrict__ bias, float* __restrict__ Out, int ldOut, int K) {
  __shared__ float As[16][132];
  __shared__ float Bs[16][68];
  const int tid = threadIdx.x;
  const int tx = tid & 15, ty = tid >> 4;
  const int m0 = blockIdx.y * 128, n0 = blockIdx.x * 64;
  const int lr = tid >> 2, lc = (tid & 3) * 4;
  float acc[8][4];
#pragma unroll
  for (int r = 0; r < 8; r++)
#pragma unroll
    for (int c = 0; c < 4; c++) acc[r][c] = 0.f;
  for (int kt = 0; kt < K; kt += 16) {
#pragma unroll
    for (int qq = 0; qq < 4; qq++) {
      int k = kt + lc + qq;
      float av0 = 0.f, av1 = 0.f, bv = 0.f;
      if (k < K) {
        av0 = In[(size_t)(m0 + lr) * ldIn + k];
        av1 = In[(size_t)(m0 + lr + 64) * ldIn + k];
        bv = W[(size_t)(n0 + lr) * K + k];
      }
      As[lc + qq][lr] = av0;
      As[lc + qq][lr + 64] = av1;
      Bs[lc + qq][lr] = bv;
    }
    __syncthreads();
#pragma unroll
    for (int kk = 0; kk < 16; kk++) {
      float4 t0 = *(const float4*)&As[kk][ty * 8];
      float4 t1 = *(const float4*)&As[kk][ty * 8 + 4];
      float4 t2 = *(const float4*)&Bs[kk][tx * 4];
      float a[8] = {t0.x, t0.y, t0.z, t0.w, t1.x, t1.y, t1.z, t1.w};
      float bb[4] = {t2.x, t2.y, t2.z, t2.w};
#pragma unroll
      for (int r = 0; r < 8; r++)
#pragma unroll
        for (int c = 0; c < 4; c++) acc[r][c] += a[r] * bb[c];
    }
    __syncthreads();
  }
  float bv[4];
#pragma unroll
  for (int c = 0; c < 4; c++) bv[c] = bias ? bias[n0 + tx * 4 + c] : 0.f;
#pragma unroll
  for (int r = 0; r < 8; r++) {
    float* op = Out + (size_t)(m0 + ty * 8 + r) * ldOut + n0 + tx * 4;
    float4 o = {acc[r][0] + bv[0], acc[r][1] + bv[1], acc[r][2] + bv[2], acc[r][3] + bv[3]};
    *(float4*)op = o;
  }
}

// ---------------------------------------------------------------------------
// LayerNorm
// ---------------------------------------------------------------------------
__global__ __launch_bounds__(256) void ln_kernel(
    const float* __restrict__ x, const float* __restrict__ w,
    const float* __restrict__ b, float* __restrict__ out) {
  const int row = blockIdx.x;
  const int tid = threadIdx.x;
  const float* xr = x + (size_t)row * Cc;
  float v0 = xr[tid], v1 = xr[tid + 256], v2 = xr[tid + 512];
  __shared__ float red[8];
  float s = v0 + v1 + v2;
#pragma unroll
  for (int o = 16; o > 0; o >>= 1) s += __shfl_xor_sync(0xffffffffu, s, o);
  if ((tid & 31) == 0) red[tid >> 5] = s;
  __syncthreads();
  float mean = (red[0] + red[1] + red[2] + red[3] + red[4] + red[5] + red[6] + red[7]) * (1.f / 768.f);
  float d0 = v0 - mean, d1 = v1 - mean, d2 = v2 - mean;
  float sq = d0 * d0 + d1 * d1 + d2 * d2;
  __syncthreads();
#pragma unroll
  for (int o = 16; o > 0; o >>= 1) sq += __shfl_xor_sync(0xffffffffu, sq, o);
  if ((tid & 31) == 0) red[tid >> 5] = sq;
  __syncthreads();
  float var = (red[0] + red[1] + red[2] + red[3] + red[4] + red[5] + red[6] + red[7]) * (1.f / 768.f);
  float inv = rsqrtf(var + 1e-5f);
  float* orow = out + (size_t)row * Cc;
  orow[tid] = d0 * inv * w[tid] + b[tid];
  orow[tid + 256] = d1 * inv * w[tid + 256] + b[tid + 256];
  orow[tid + 512] = d2 * inv * w[tid + 512] + b[tid + 512];
}

// ---------------------------------------------------------------------------
// Embed
// ---------------------------------------------------------------------------
__global__ __launch_bounds__(256) void embed_kernel(
    const int* __restrict__ iu, const int* __restrict__ idn,
    const float* __restrict__ tu, const float* __restrict__ td,
    const float* __restrict__ pos, float* __restrict__ x) {
  int gidx = blockIdx.x * 256 + threadIdx.x;
  int c = gidx % Cc;
  int row = gidx / Cc;
  int i = row % Tt;
  int b = row / Tt;
  float p = pos[i * Cc + c];
  if (i < tt) x[gidx] += p;
  else if (i < 2 * tt) x[gidx] = tu[(size_t)iu[b * tt + (i - tt)] * Cc + c] + p;
  else x[gidx] = td[(size_t)idn[b * tt + (i - 2 * tt)] * Cc + c] + p;
}

// ---------------------------------------------------------------------------
// tf32 flash attention (unchanged; GEMM pipe is the current bottleneck)
// ---------------------------------------------------------------------------
__device__ __forceinline__ unsigned f2tf_a(float f) { return f2tf(f); }

__global__ __launch_bounds__(128) void attn_tf32(
    const float* __restrict__ qkv, float* __restrict__ y) {
  extern __shared__ unsigned smx[];
  unsigned (*Qt)[72] = (unsigned(*)[72])smx;
  unsigned (*Kt)[72] = (unsigned(*)[72])(smx + 64 * 72);
  unsigned (*Vs)[73] = (unsigned(*)[73])(smx + 2 * 64 * 72);
  unsigned (*Ps)[72] = (unsigned(*)[72])(smx + 2 * 64 * 72 + 64 * 73);

  const int qt = blockIdx.x, h = blockIdx.y, b = blockIdx.z;
  const int tid = threadIdx.x, lane = tid & 31, warp = tid >> 5;
  const int g = lane >> 2, q = lane & 3;

  {
    int i = tid & 63, ds = (tid >> 6) * 32;
    const float* qr = qkv + (size_t)(b * Tt + qt * 64 + i) * 2304 + h * 64 + ds;
#pragma unroll
    for (int j = 0; j < 8; j++) {
      float4 v = *(const float4*)(qr + j * 4);
      Qt[ds + j * 4 + 0][i] = f2tf_a(v.x);
      Qt[ds + j * 4 + 1][i] = f2tf_a(v.y);
      Qt[ds + j * 4 + 2][i] = f2tf_a(v.z);
      Qt[ds + j * 4 + 3][i] = f2tf_a(v.w);
    }
  }

  float m0r = -1e30f, m1r = -1e30f, l0 = 0.f, l1 = 0.f;
  float accO[8][4];
#pragma unroll
  for (int nb = 0; nb < 8; nb++)
#pragma unroll
    for (int r = 0; r < 4; r++) accO[nb][r] = 0.f;

  const int a = qt & 3;
  const int r0 = warp * 16 + g, r1 = r0 + 8;

  for (int kt = 0; kt < 12; kt++) {
    if ((kt & 3) > a) continue;
    const bool diag = ((kt & 3) == a);
    __syncthreads();
    {
      int j = tid & 63, ds = (tid >> 6) * 32;
      const float* kr = qkv + (size_t)(b * Tt + kt * 64 + j) * 2304 + 768 + h * 64 + ds;
      const float* vr = kr + 768;
#pragma unroll
      for (int jj = 0; jj < 8; jj++) {
        float4 kv = *(const float4*)(kr + jj * 4);
        Kt[ds + jj * 4 + 0][j] = f2tf_a(kv.x);
        Kt[ds + jj * 4 + 1][j] = f2tf_a(kv.y);
        Kt[ds + jj * 4 + 2][j] = f2tf_a(kv.z);
        Kt[ds + jj * 4 + 3][j] = f2tf_a(kv.w);
        float4 vv = *(const float4*)(vr + jj * 4);
        Vs[j][ds + jj * 4 + 0] = f2tf_a(vv.x);
        Vs[j][ds + jj * 4 + 1] = f2tf_a(vv.y);
        Vs[j][ds + jj * 4 + 2] = f2tf_a(vv.z);
        Vs[j][ds + jj * 4 + 3] = f2tf_a(vv.w);
      }
    }
    __syncthreads();

    float s[8][4];
#pragma unroll
    for (int nb = 0; nb < 8; nb++)
#pragma unroll
      for (int r = 0; r < 4; r++) s[nb][r] = 0.f;
#pragma unroll
    for (int ks = 0; ks < 8; ks++) {
      const int k0 = ks * 8;
      unsigned aa[4] = {Qt[k0 + q][r0], Qt[k0 + q][r1], Qt[k0 + q + 4][r0], Qt[k0 + q + 4][r1]};
#pragma unroll
      for (int nb = 0; nb < 8; nb++) {
        unsigned bb[2] = {Kt[k0 + q][nb * 8 + g], Kt[k0 + q + 4][nb * 8 + g]};
        mma8(s[nb], aa, bb);
      }
    }

    float mx0 = -1e30f, mx1 = -1e30f;
#pragma unroll
    for (int nb = 0; nb < 8; nb++) {
      int c0 = nb * 8 + 2 * q;
      float v00 = s[nb][0] * 0.125f, v01 = s[nb][1] * 0.125f;
      float v10 = s[nb][2] * 0.125f, v11 = s[nb][3] * 0.125f;
      if (diag) {
        if (c0 > r0) v00 = -1e30f;
        if (c0 + 1 > r0) v01 = -1e30f;
        if (c0 > r1) v10 = -1e30f;
        if (c0 + 1 > r1) v11 = -1e30f;
      }
      s[nb][0] = v00; s[nb][1] = v01; s[nb][2] = v10; s[nb][3] = v11;
      mx0 = fmaxf(mx0, fmaxf(v00, v01));
      mx1 = fmaxf(mx1, fmaxf(v10, v11));
    }
    mx0 = fmaxf(mx0, __shfl_xor_sync(0xffffffffu, mx0, 1));
    mx0 = fmaxf(mx0, __shfl_xor_sync(0xffffffffu, mx0, 2));
    mx1 = fmaxf(mx1, __shfl_xor_sync(0xffffffffu, mx1, 1));
    mx1 = fmaxf(mx1, __shfl_xor_sync(0xffffffffu, mx1, 2));

    float mn0 = fmaxf(m0r, mx0), mn1 = fmaxf(m1r, mx1);
    float cf0 = __expf(m0r - mn0), cf1 = __expf(m1r - mn1);
    m0r = mn0; m1r = mn1;

    float rs0 = 0.f, rs1 = 0.f;
#pragma unroll
    for (int nb = 0; nb < 8; nb++) {
      int c0 = nb * 8 + 2 * q;
      float p00 = __expf(s[nb][0] - mn0);
      float p01 = __expf(s[nb][1] - mn0);
      float p10 = __expf(s[nb][2] - mn1);
      float p11 = __expf(s[nb][3] - mn1);
      rs0 += p00 + p01;
      rs1 += p10 + p11;
      Ps[c0][r0] = f2tf_a(p00);
      Ps[c0 + 1][r0] = f2tf_a(p01);
      Ps[c0][r1] = f2tf_a(p10);
      Ps[c0 + 1][r1] = f2tf_a(p11);
    }
    rs0 += __shfl_xor_sync(0xffffffffu, rs0, 1);
    rs0 += __shfl_xor_sync(0xffffffffu, rs0, 2);
    rs1 += __shfl_xor_sync(0xffffffffu, rs1, 1);
    rs1 += __shfl_xor_sync(0xffffffffu, rs1, 2);
    l0 = l0 * cf0 + rs0;
    l1 = l1 * cf1 + rs1;
#pragma unroll
    for (int nb = 0; nb < 8; nb++) {
      accO[nb][0] *= cf0; accO[nb][1] *= cf0;
      accO[nb][2] *= cf1; accO[nb][3] *= cf1;
    }
    __syncthreads();

#pragma unroll
    for (int ks = 0; ks < 8; ks++) {
      const int k0 = ks * 8;
      unsigned aa[4] = {Ps[k0 + q][r0], Ps[k0 + q][r1], Ps[k0 + q + 4][r0], Ps[k0 + q + 4][r1]};
#pragma unroll
      for (int nb = 0; nb < 8; nb++) {
        unsigned bb[2] = {Vs[k0 + q][nb * 8 + g], Vs[k0 + q + 4][nb * 8 + g]};
        mma8(accO[nb], aa, bb);
      }
    }
  }

  float inv0 = 1.f / l0, inv1 = 1.f / l1;
#pragma unroll
  for (int nb = 0; nb < 8; nb++) {
    int c0 = nb * 8 + 2 * q;
    float* y0 = y + (size_t)(b * Tt + qt * 64 + r0) * Cc + h * 64 + c0;
    *(float2*)y0 = make_float2(accO[nb][0] * inv0, accO[nb][1] * inv0);
    *(float2*)(y0 + 8 * Cc) = make_float2(accO[nb][2] * inv1, accO[nb][3] * inv1);
  }
}

// ---------------------------------------------------------------------------
// Launcher
// ---------------------------------------------------------------------------
extern "C" void kernel_launch(void* const* d_in, const int* in_sizes, int n_in,
                              void* d_out, int out_size) {
  const int* idx_up = nullptr; const int* idx_down = nullptr;
  const float *cond = 0, *tok_up = 0, *tok_down = 0, *pos = 0, *cond_w = 0, *cond_b = 0;
  const float *lnf_w = 0, *lnf_b = 0, *hup = 0, *hdn = 0;
  const float *ln1[2] = {0, 0}, *ln2[2] = {0, 0}, *qkvw[2] = {0, 0}, *qkvb[2] = {0, 0};
  const float *projw[2] = {0, 0}, *projb[2] = {0, 0};
  const float *fc1w[2] = {0, 0}, *fc1b[2] = {0, 0}, *fc2w[2] = {0, 0}, *fc2b[2] = {0, 0};

  int c512 = 0, c393 = 0, c768 = 0, c9216 = 0, cqw = 0, cqb = 0, cpw = 0, c4608 = 0,
      cfw = 0, cfb = 0;
  for (int i = 0; i < n_in; i++) {
    const float* f = (const float*)d_in[i];
    switch (in_sizes[i]) {
      case 512:       if (c512 == 0) idx_up = (const int*)f; else idx_down = (const int*)f; c512++; break;
      case 224256:    cond = f; break;
      case 393216:    if (c393 == 0) tok_up = f; else if (c393 == 1) tok_down = f;
                      else if (c393 == 2) hup = f; else hdn = f; c393++; break;
      case 589824:    pos = f; break;
      case 336384:    cond_w = f; break;
      case 768:       if (c768 == 0) cond_b = f; else if (c768 == 1) lnf_w = f; else lnf_b = f; c768++; break;
      case 9216:      if (c9216 == 0) ln1[0] = f; else if (c9216 == 1) ln2[0] = f;
                      else if (c9216 == 2) ln1[1] = f; else ln2[1] = f; c9216++; break;
      case 10616832:  qkvw[cqw++] = f; break;
      case 13824:     qkvb[cqb++] = f; break;
      case 3538944:   projw[cpw++] = f; break;
      case 4608:      if (c4608 == 0) projb[0] = f; else if (c4608 == 1) fc2b[0] = f;
                      else if (c4608 == 2) projb[1] = f; else fc2b[1] = f; c4608++; break;
      case 14155776:  if (cfw == 0) fc1w[0] = f; else if (cfw == 1) fc2w[0] = f;
                      else if (cfw == 2) fc1w[1] = f; else fc2w[1] = f; cfw++; break;
      case 18432:     fc1b[cfb++] = f; break;
      default: break;
    }
  }

  float *x, *h, *y, *big;
  cudaGetSymbolAddress((void**)&x, g_x);
  cudaGetSymbolAddress((void**)&h, g_h);
  cudaGetSymbolAddress((void**)&y, g_y);
  cudaGetSymbolAddress((void**)&big, g_big);

  const int ATTN_SMEM = (2 * 64 * 72 + 64 * 73 + 64 * 72) * 4;  // 73984
  cudaFuncSetAttribute(attn_tf32, cudaFuncAttributeMaxDynamicSharedMemorySize, ATTN_SMEM);

  // --- Embed ---
  for (int b = 0; b < Bz; b++)
    gemm_f32<<<dim3(Cc / 64, tt / 128), 256>>>(
        cond + (size_t)b * tt * 438, 438, cond_w, cond_b, x + (size_t)b * Tt * Cc, Cc, 438);
  embed_kernel<<<(Bz * Tt * Cc) / 256, 256>>>(idx_up, idx_down, tok_up, tok_down, pos, x);

  // --- 2 stacks x 6 blocks ---
  for (int st = 0; st < 2; st++) {
    for (int l = 0; l < 6; l++) {
      const float* w1 = ln1[st] + (size_t)l * 2 * Cc;
      ln_kernel<<<Bz * Tt, 256>>>(x, w1, w1 + Cc, h);
      gemm_h<128, 0><<<dim3(3 * Cc / 128, Bz * Tt / 128), 256>>>(
          h, Cc, qkvw[st] + (size_t)l * 3 * Cc * Cc, qkvb[st] + (size_t)l * 3 * Cc,
          big, 3 * Cc, Cc);
      attn_tf32<<<dim3(Tt / 64, Hh, Bz), 128, ATTN_SMEM>>>(big, y);
      gemm_h<64, 2><<<dim3(Cc / 128, Bz * Tt / 64), 256>>>(
          y, Cc, projw[st] + (size_t)l * Cc * Cc, projb[st] + (size_t)l * Cc, x, Cc, Cc);
      const float* w2 = ln2[st] + (size_t)l * 2 * Cc;
      ln_kernel<<<Bz * Tt, 256>>>(x, w2, w2 + Cc, h);
      gemm_h<128, 1><<<dim3(FC / 128, Bz * Tt / 128), 256>>>(
          h, Cc, fc1w[st] + (size_t)l * FC * Cc, fc1b[st] + (size_t)l * FC, big, FC, Cc);
      gemm_h<64, 2><<<dim3(Cc / 128, Bz * Tt / 64), 256>>>(
          big, FC, fc2w[st] + (size_t)l * Cc * FC, fc2b[st] + (size_t)l * Cc, x, Cc, FC);
    }
  }

  // --- Final LN + heads ---
  ln_kernel<<<Bz * Tt, 256>>>(x, lnf_w, lnf_b, h);
  float* out = (float*)d_out;
  for (int b = 0; b < Bz; b++) {
    gemm_h<64, 0><<<dim3(Vv / 128, tt / 64), 256>>>(
        h + (size_t)(b * Tt + tt) * Cc, Cc, hup, nullptr, out + (size_t)b * tt * Vv, Vv, Cc);
    gemm_h<64, 0><<<dim3(Vv / 128, tt / 64), 256>>>(
        h + (size_t)(b * Tt + 2 * tt) * Cc, Cc, hdn, nullptr,
        out + (size_t)(Bz * tt * Vv) + (size_t)b * tt * Vv, Vv, Cc);
  }
  (void)out_size; (void)n_in;
}